// round 1
// baseline (speedup 1.0000x reference)
#include <cuda_runtime.h>
#include <cuda_bf16.h>
#include <math.h>

// Fixed problem constants (reference hardcodes these)
#define HEADS   8
#define PTS     4
#define DHEAD   32
#define CH      256            // cin = cout = 256
#define MAXROWS 32768          // bs * h * w = 2 * 128 * 128

// Scratch (allocation-free rule: __device__ globals)
__device__ float g_v[MAXROWS * CH];        // value @ W_val  (32 MB)
__device__ float g_off[MAXROWS * HEADS * PTS * 2];  // 8 MB
__device__ float g_lg[MAXROWS * HEADS * PTS];       // 4 MB
__device__ float g_attn[MAXROWS * CH];     // sampled output (32 MB)

// ---------------------------------------------------------------------------
// SGEMM: C[M,N] = A[M,K] @ B[K,N] + bias[N] (+ resid[M,N] if non-null)
// Tiles: 128 (M) x 64 (N) x 16 (K). 256 threads, 8x4 micro-tile per thread.
// Requires M % 128 == 0, K % 16 == 0, N % 4 == 0. N may be < 64 (guarded).
// ---------------------------------------------------------------------------
#define MT 128
#define NT 64
#define KT 16

__global__ __launch_bounds__(256) void sgemm_bias(
    const float* __restrict__ A, const float* __restrict__ B,
    const float* __restrict__ bias, const float* __restrict__ resid,
    float* __restrict__ C, int M, int N, int K)
{
    __shared__ float As[KT][MT];   // A tile, transposed: As[k][m]
    __shared__ float Bs[KT][NT];   // B tile: Bs[k][n]

    const int tid = threadIdx.x;
    const int m0 = blockIdx.y * MT;
    const int n0 = blockIdx.x * NT;
    const int tx = tid & 15;       // n micro index (16 * 4 = 64)
    const int ty = tid >> 4;       // m micro index (16 * 8 = 128)

    float acc[8][4];
#pragma unroll
    for (int i = 0; i < 8; i++)
#pragma unroll
        for (int j = 0; j < 4; j++) acc[i][j] = 0.f;

    for (int k0 = 0; k0 < K; k0 += KT) {
        // Load A tile: 128x16 = 512 float4, 2 per thread
#pragma unroll
        for (int i = 0; i < 2; i++) {
            int f  = tid * 2 + i;         // 0..511
            int r  = f >> 2;              // row in tile (0..127)
            int c4 = f & 3;               // float4 within 16-wide k slice
            float4 a = *(const float4*)&A[(size_t)(m0 + r) * K + k0 + c4 * 4];
            As[c4 * 4 + 0][r] = a.x;
            As[c4 * 4 + 1][r] = a.y;
            As[c4 * 4 + 2][r] = a.z;
            As[c4 * 4 + 3][r] = a.w;
        }
        // Load B tile: 16x64 = 256 float4, 1 per thread
        {
            int r  = tid >> 4;            // k row (0..15)
            int c4 = tid & 15;            // n float4 (0..15)
            int n  = n0 + c4 * 4;
            float4 b = make_float4(0.f, 0.f, 0.f, 0.f);
            if (n < N) b = *(const float4*)&B[(size_t)(k0 + r) * N + n];
            *(float4*)&Bs[r][c4 * 4] = b;
        }
        __syncthreads();

#pragma unroll
        for (int k = 0; k < KT; k++) {
            float4 a0 = *(const float4*)&As[k][ty * 8];
            float4 a1 = *(const float4*)&As[k][ty * 8 + 4];
            float4 bv = *(const float4*)&Bs[k][tx * 4];
            float a[8] = {a0.x, a0.y, a0.z, a0.w, a1.x, a1.y, a1.z, a1.w};
            float b[4] = {bv.x, bv.y, bv.z, bv.w};
#pragma unroll
            for (int i = 0; i < 8; i++)
#pragma unroll
                for (int j = 0; j < 4; j++)
                    acc[i][j] = fmaf(a[i], b[j], acc[i][j]);
        }
        __syncthreads();
    }

#pragma unroll
    for (int i = 0; i < 8; i++) {
        int m = m0 + ty * 8 + i;
#pragma unroll
        for (int j = 0; j < 4; j++) {
            int n = n0 + tx * 4 + j;
            if (n < N) {
                float vv = acc[i][j] + bias[n];
                if (resid) vv += resid[(size_t)m * N + n];
                C[(size_t)m * N + n] = vv;
            }
        }
    }
}

// ---------------------------------------------------------------------------
// Deformable bilinear sampling + softmax over points.
// One block per query row; 8 warps = 8 heads; lane = channel within head.
// ix = qx + off_x, iy = qy + off_y (exact algebraic collapse of the
// reference's normalize->grid->denormalize chain).
// ---------------------------------------------------------------------------
__global__ __launch_bounds__(256) void sample_kernel(
    const float* __restrict__ v, const float* __restrict__ off,
    const float* __restrict__ logits, float* __restrict__ out,
    const int* __restrict__ hptr, const int* __restrict__ wptr)
{
    const int h = *hptr, w = *wptr;
    const int HW = h * w;
    const int row  = blockIdx.x;
    const int head = threadIdx.x >> 5;
    const int lane = threadIdx.x & 31;

    const int b  = row / HW;
    const int q  = row - b * HW;
    const int qy = q / w;
    const int qx = q - qy * w;

    // softmax over the 4 points of this head
    const float* lg = &logits[(size_t)row * (HEADS * PTS) + head * PTS];
    float l0 = lg[0], l1 = lg[1], l2 = lg[2], l3 = lg[3];
    float mx = fmaxf(fmaxf(l0, l1), fmaxf(l2, l3));
    float e0 = expf(l0 - mx), e1 = expf(l1 - mx);
    float e2 = expf(l2 - mx), e3 = expf(l3 - mx);
    float inv = 1.f / (e0 + e1 + e2 + e3);
    float aw[PTS] = {e0 * inv, e1 * inv, e2 * inv, e3 * inv};

    const float* of = &off[(size_t)row * (HEADS * PTS * 2) + head * (PTS * 2)];
    const float* vb = v + (size_t)b * HW * CH + head * DHEAD + lane;

    float acc = 0.f;
#pragma unroll
    for (int p = 0; p < PTS; p++) {
        float ix = (float)qx + of[p * 2 + 0];
        float iy = (float)qy + of[p * 2 + 1];
        float x0f = floorf(ix), y0f = floorf(iy);
        int x0 = (int)x0f, y0 = (int)y0f;
        float wx1 = ix - x0f, wy1 = iy - y0f;
        float wx0 = 1.f - wx1, wy0 = 1.f - wy1;

        bool vx0 = (x0 >= 0) && (x0 < w);
        bool vx1 = (x0 + 1 >= 0) && (x0 + 1 < w);
        bool vy0 = (y0 >= 0) && (y0 < h);
        bool vy1 = (y0 + 1 >= 0) && (y0 + 1 < h);

        float s = 0.f;
        if (vy0 && vx0) s += wx0 * wy0 * vb[(size_t)(y0 * w + x0) * CH];
        if (vy0 && vx1) s += wx1 * wy0 * vb[(size_t)(y0 * w + x0 + 1) * CH];
        if (vy1 && vx0) s += wx0 * wy1 * vb[(size_t)((y0 + 1) * w + x0) * CH];
        if (vy1 && vx1) s += wx1 * wy1 * vb[(size_t)((y0 + 1) * w + x0 + 1) * CH];
        acc += aw[p] * s;
    }
    out[(size_t)row * CH + head * DHEAD + lane] = acc;
}

// ---------------------------------------------------------------------------

extern "C" void kernel_launch(void* const* d_in, const int* in_sizes, int n_in,
                              void* d_out, int out_size)
{
    const float* query  = (const float*)d_in[0];
    const float* value  = (const float*)d_in[1];
    const float* W_off  = (const float*)d_in[2];
    const float* b_off  = (const float*)d_in[3];
    const float* W_attn = (const float*)d_in[4];
    const float* b_attn = (const float*)d_in[5];
    const float* W_val  = (const float*)d_in[6];
    const float* b_val  = (const float*)d_in[7];
    const float* W_out  = (const float*)d_in[8];
    const float* b_out  = (const float*)d_in[9];
    const int*   hp     = (const int*)d_in[10];
    const int*   wp     = (const int*)d_in[11];
    float* out = (float*)d_out;

    const int K = in_sizes[2] / (HEADS * PTS * 2);  // cin = 256
    const int M = in_sizes[0] / K;                  // rows = bs*h*w = 32768
    const int N = in_sizes[6] / K;                  // cout = 256

    float *gv, *goff, *glg, *gattn;
    cudaGetSymbolAddress((void**)&gv,    g_v);
    cudaGetSymbolAddress((void**)&goff,  g_off);
    cudaGetSymbolAddress((void**)&glg,   g_lg);
    cudaGetSymbolAddress((void**)&gattn, g_attn);

    dim3 blk(256);
    // 1. v = value @ W_val + b_val
    sgemm_bias<<<dim3(N / NT, M / MT), blk>>>(value, W_val, b_val, nullptr, gv, M, N, K);
    // 2. off = query @ W_off + b_off
    sgemm_bias<<<dim3(1, M / MT), blk>>>(query, W_off, b_off, nullptr, goff, M, HEADS * PTS * 2, K);
    // 3. logits = query @ W_attn + b_attn
    sgemm_bias<<<dim3(1, M / MT), blk>>>(query, W_attn, b_attn, nullptr, glg, M, HEADS * PTS, K);
    // 4. deformable sampling (+ per-head softmax over points)
    sample_kernel<<<M, 256>>>(gv, goff, glg, gattn, hp, wp);
    // 5. out = attn @ W_out + b_out + query
    sgemm_bias<<<dim3(N / NT, M / MT), blk>>>(gattn, W_out, b_out, query, out, M, N, K);
}

// round 2
// speedup vs baseline: 1.7903x; 1.7903x over previous
#include <cuda_runtime.h>
#include <cuda_bf16.h>
#include <math.h>
#include <stdint.h>

#define HEADS   8
#define PTS     4
#define CH      256
#define MAXROWS 32768

// Scratch (__device__ globals per allocation-free rule)
__device__ float g_v[MAXROWS * CH];                 // value @ W_val
__device__ float g_offlg[MAXROWS * 96];             // [off(64) | logits(32)] per row
__device__ float g_attn[MAXROWS * CH];              // sampled output
__device__ float g_Wp[CH * 96];                     // packed [W_off | W_attn]
__device__ float g_bp[96];

// ---------------------------------------------------------------------------
// tf32 tensor-core GEMM: C[M,N] = A[M,K] @ B[K,N] + bias[N] (+ resid)
// Block tile 128x128x32, 256 thr = 8 warps (2m x 4n), warp tile 64x32.
// mma.sync.aligned.m16n8k8.row.col.f32.tf32.tf32.f32
// Requires M%128==0, K%32==0, N%4==0 (N guarded vs 128 tile).
// ---------------------------------------------------------------------------
__device__ __forceinline__ uint32_t f2tf32(float x) {
    uint32_t r;
    asm("cvt.rna.tf32.f32 %0, %1;" : "=r"(r) : "f"(x));
    return r;
}

__global__ __launch_bounds__(256) void gemm_tf32(
    const float* __restrict__ A, const float* __restrict__ B,
    const float* __restrict__ bias, const float* __restrict__ resid,
    float* __restrict__ C, int M, int N, int K)
{
    __shared__ __align__(16) uint32_t As[128][36];   // [m][k], pad 36 -> conflict-free frag reads
    __shared__ __align__(16) uint32_t Bs[32][136];   // [k][n], pad 136

    const int tid  = threadIdx.x;
    const int lane = tid & 31;
    const int warp = tid >> 5;
    const int wm   = warp & 1;        // 2 warps along M
    const int wn   = warp >> 1;       // 4 warps along N
    const int m0   = blockIdx.y * 128;
    const int n0   = blockIdx.x * 128;
    const int lr   = lane >> 2;       // 0..7
    const int lc   = lane & 3;        // 0..3

    float acc[4][4][4];
#pragma unroll
    for (int i = 0; i < 4; i++)
#pragma unroll
        for (int j = 0; j < 4; j++)
#pragma unroll
            for (int v = 0; v < 4; v++) acc[i][j][v] = 0.f;

    for (int k0 = 0; k0 < K; k0 += 32) {
        // Stage A tile 128x32: 1024 float4, 4 per thread
#pragma unroll
        for (int i = 0; i < 4; i++) {
            int f  = tid + i * 256;
            int r  = f >> 3;
            int c4 = f & 7;
            float4 a = *(const float4*)&A[(size_t)(m0 + r) * K + k0 + c4 * 4];
            uint4 t;
            t.x = f2tf32(a.x); t.y = f2tf32(a.y);
            t.z = f2tf32(a.z); t.w = f2tf32(a.w);
            *(uint4*)&As[r][c4 * 4] = t;
        }
        // Stage B tile 32x128: 1024 float4, 4 per thread (N-guarded)
#pragma unroll
        for (int i = 0; i < 4; i++) {
            int f  = tid + i * 256;
            int kk = f >> 5;
            int c4 = f & 31;
            int n  = n0 + c4 * 4;
            float4 b = make_float4(0.f, 0.f, 0.f, 0.f);
            if (n < N) b = *(const float4*)&B[(size_t)(k0 + kk) * N + n];
            uint4 t;
            t.x = f2tf32(b.x); t.y = f2tf32(b.y);
            t.z = f2tf32(b.z); t.w = f2tf32(b.w);
            *(uint4*)&Bs[kk][c4 * 4] = t;
        }
        __syncthreads();

#pragma unroll
        for (int ks = 0; ks < 32; ks += 8) {
            uint32_t af[4][4];
#pragma unroll
            for (int ma = 0; ma < 4; ma++) {
                int r = wm * 64 + ma * 16 + lr;
                af[ma][0] = As[r    ][ks + lc];
                af[ma][1] = As[r + 8][ks + lc];
                af[ma][2] = As[r    ][ks + 4 + lc];
                af[ma][3] = As[r + 8][ks + 4 + lc];
            }
            uint32_t bf[4][2];
#pragma unroll
            for (int na = 0; na < 4; na++) {
                int n = wn * 32 + na * 8 + lr;
                bf[na][0] = Bs[ks + lc    ][n];
                bf[na][1] = Bs[ks + 4 + lc][n];
            }
#pragma unroll
            for (int ma = 0; ma < 4; ma++)
#pragma unroll
                for (int na = 0; na < 4; na++) {
                    asm volatile(
                        "mma.sync.aligned.m16n8k8.row.col.f32.tf32.tf32.f32 "
                        "{%0,%1,%2,%3}, {%4,%5,%6,%7}, {%8,%9}, {%0,%1,%2,%3};\n"
                        : "+f"(acc[ma][na][0]), "+f"(acc[ma][na][1]),
                          "+f"(acc[ma][na][2]), "+f"(acc[ma][na][3])
                        : "r"(af[ma][0]), "r"(af[ma][1]), "r"(af[ma][2]), "r"(af[ma][3]),
                          "r"(bf[na][0]), "r"(bf[na][1]));
                }
        }
        __syncthreads();
    }

    // Epilogue
#pragma unroll
    for (int ma = 0; ma < 4; ma++) {
        int r0 = m0 + wm * 64 + ma * 16 + lr;
        int r1 = r0 + 8;
#pragma unroll
        for (int na = 0; na < 4; na++) {
            int c = n0 + wn * 32 + na * 8 + lc * 2;
            if (c < N) {
                float b0 = bias[c], b1 = bias[c + 1];
                float v00 = acc[ma][na][0] + b0;
                float v01 = acc[ma][na][1] + b1;
                float v10 = acc[ma][na][2] + b0;
                float v11 = acc[ma][na][3] + b1;
                if (resid) {
                    v00 += resid[(size_t)r0 * N + c];
                    v01 += resid[(size_t)r0 * N + c + 1];
                    v10 += resid[(size_t)r1 * N + c];
                    v11 += resid[(size_t)r1 * N + c + 1];
                }
                C[(size_t)r0 * N + c]     = v00;
                C[(size_t)r0 * N + c + 1] = v01;
                C[(size_t)r1 * N + c]     = v10;
                C[(size_t)r1 * N + c + 1] = v11;
            }
        }
    }
}

// ---------------------------------------------------------------------------
// Pack [W_off | W_attn] -> g_Wp (256x96), [b_off | b_attn] -> g_bp (96)
// ---------------------------------------------------------------------------
__global__ void pack_small(const float* __restrict__ W_off, const float* __restrict__ b_off,
                           const float* __restrict__ W_attn, const float* __restrict__ b_attn,
                           float* __restrict__ Wp, float* __restrict__ bp)
{
    int i = blockIdx.x * blockDim.x + threadIdx.x;   // 0 .. 24575
    int k = i / 96, n = i - k * 96;
    Wp[i] = (n < 64) ? W_off[k * 64 + n] : W_attn[k * 32 + (n - 64)];
    if (i < 96) bp[i] = (i < 64) ? b_off[i] : b_attn[i - 64];
}

// ---------------------------------------------------------------------------
// Deformable bilinear sampling + per-head softmax. One block/row, warp=head,
// lane=channel. All-int32 addressing, CH=256 via shifts.
// ---------------------------------------------------------------------------
__global__ __launch_bounds__(256) void sample_kernel(
    const float* __restrict__ v, const float* __restrict__ offlg,
    float* __restrict__ out,
    const int* __restrict__ hptr, const int* __restrict__ wptr)
{
    const int h = *hptr, w = *wptr;
    const int HW = h * w;
    const int row  = blockIdx.x;
    const int head = threadIdx.x >> 5;
    const int lane = threadIdx.x & 31;

    const int b  = row / HW;
    const int q  = row - b * HW;
    const int qy = q / w;
    const int qx = q - qy * w;

    const float* base = offlg + row * 96;
    const float* lg = base + 64 + head * 4;
    float l0 = lg[0], l1 = lg[1], l2 = lg[2], l3 = lg[3];
    float mx = fmaxf(fmaxf(l0, l1), fmaxf(l2, l3));
    float e0 = __expf(l0 - mx), e1 = __expf(l1 - mx);
    float e2 = __expf(l2 - mx), e3 = __expf(l3 - mx);
    float inv = 1.f / (e0 + e1 + e2 + e3);
    float aw[PTS] = {e0 * inv, e1 * inv, e2 * inv, e3 * inv};

    const float* of = base + head * 8;
    const float* vb = v + ((b * HW) << 8) + head * 32 + lane;
    const int wstride = w << 8;

    float acc = 0.f;
#pragma unroll
    for (int p = 0; p < PTS; p++) {
        float ix = (float)qx + of[p * 2 + 0];
        float iy = (float)qy + of[p * 2 + 1];
        float xf = floorf(ix), yf = floorf(iy);
        int x0 = (int)xf, y0 = (int)yf;
        float wx1 = ix - xf, wy1 = iy - yf;
        float wx0 = 1.f - wx1, wy0 = 1.f - wy1;

        bool vx0 = (unsigned)x0 < (unsigned)w;
        bool vx1 = (unsigned)(x0 + 1) < (unsigned)w;
        bool vy0 = (unsigned)y0 < (unsigned)h;
        bool vy1 = (unsigned)(y0 + 1) < (unsigned)h;

        int o00 = (y0 * w + x0) << 8;    // negative only when masked off
        float s = 0.f;
        if (vy0 && vx0) s = fmaf(wx0 * wy0, vb[o00], s);
        if (vy0 && vx1) s = fmaf(wx1 * wy0, vb[o00 + 256], s);
        if (vy1 && vx0) s = fmaf(wx0 * wy1, vb[o00 + wstride], s);
        if (vy1 && vx1) s = fmaf(wx1 * wy1, vb[o00 + wstride + 256], s);
        acc = fmaf(aw[p], s, acc);
    }
    out[(row << 8) + head * 32 + lane] = acc;
}

// ---------------------------------------------------------------------------

extern "C" void kernel_launch(void* const* d_in, const int* in_sizes, int n_in,
                              void* d_out, int out_size)
{
    const float* query  = (const float*)d_in[0];
    const float* value  = (const float*)d_in[1];
    const float* W_off  = (const float*)d_in[2];
    const float* b_off  = (const float*)d_in[3];
    const float* W_attn = (const float*)d_in[4];
    const float* b_attn = (const float*)d_in[5];
    const float* W_val  = (const float*)d_in[6];
    const float* b_val  = (const float*)d_in[7];
    const float* W_out  = (const float*)d_in[8];
    const float* b_out  = (const float*)d_in[9];
    const int*   hp     = (const int*)d_in[10];
    const int*   wp     = (const int*)d_in[11];
    float* out = (float*)d_out;

    const int K = in_sizes[2] / (HEADS * PTS * 2);   // 256
    const int M = in_sizes[0] / K;                   // 32768
    const int N = in_sizes[6] / K;                   // 256

    float *gv, *gofflg, *gattn, *gWp, *gbp;
    cudaGetSymbolAddress((void**)&gv,     g_v);
    cudaGetSymbolAddress((void**)&gofflg, g_offlg);
    cudaGetSymbolAddress((void**)&gattn,  g_attn);
    cudaGetSymbolAddress((void**)&gWp,    g_Wp);
    cudaGetSymbolAddress((void**)&gbp,    g_bp);

    // 0. pack small weights [W_off | W_attn]
    pack_small<<<(K * 96) / 256, 256>>>(W_off, b_off, W_attn, b_attn, gWp, gbp);
    // 1. v = value @ W_val + b_val
    gemm_tf32<<<dim3((N + 127) / 128, M / 128), 256>>>(value, W_val, b_val, nullptr, gv, M, N, K);
    // 2+3. [off | logits] = query @ [W_off | W_attn] + [b_off | b_attn]
    gemm_tf32<<<dim3(1, M / 128), 256>>>(query, gWp, gbp, nullptr, gofflg, M, 96, K);
    // 4. deformable sampling (+ per-head softmax over points)
    sample_kernel<<<M, 256>>>(gv, gofflg, gattn, hp, wp);
    // 5. out = attn @ W_out + b_out + query
    gemm_tf32<<<dim3((N + 127) / 128, M / 128), 256>>>(gattn, W_out, b_out, query, out, M, N, K);
}

// round 3
// speedup vs baseline: 2.4407x; 1.3633x over previous
#include <cuda_runtime.h>
#include <cuda_bf16.h>
#include <math.h>
#include <stdint.h>

#define HEADS   8
#define PTS     4
#define CH      256
#define MAXROWS 32768

// Scratch (__device__ globals per allocation-free rule)
__device__ float g_v[MAXROWS * CH];                 // value @ W_val
__device__ float g_offlg[MAXROWS * 96];             // [off(64) | logits(32)] per row
__device__ float g_attn[MAXROWS * CH];              // sampled output
__device__ float g_Wp[CH * 96];                     // packed [W_off | W_attn]
__device__ float g_bp[96];

// ---------------------------------------------------------------------------
// tf32 tensor-core GEMM, cp.async double-buffered.
// C[M,N] = A[M,K] @ B[K,N] + bias[N] (+ resid)
// Block tile 128x128x32, 256 thr = 8 warps (2m x 4n), warp tile 64x32.
// ---------------------------------------------------------------------------
__device__ __forceinline__ uint32_t f2tf32(float x) {
    uint32_t r;
    asm("cvt.rna.tf32.f32 %0, %1;" : "=r"(r) : "f"(x));
    return r;
}

__device__ __forceinline__ void cpasync16(float* dst_smem, const float* src, bool pred) {
    uint32_t d = (uint32_t)__cvta_generic_to_shared(dst_smem);
    int sz = pred ? 16 : 0;
    asm volatile("cp.async.cg.shared.global [%0], [%1], 16, %2;\n"
                 :: "r"(d), "l"(src), "r"(sz));
}

#define AS_LD 36      // padded row (floats), 16B-aligned rows
#define BS_LD 136
#define ASZ (128 * AS_LD)
#define BSZ (32 * BS_LD)
#define GEMM_SMEM ((2 * ASZ + 2 * BSZ) * 4)

__global__ __launch_bounds__(256) void gemm_tf32(
    const float* __restrict__ A, const float* __restrict__ B,
    const float* __restrict__ bias, const float* __restrict__ resid,
    float* __restrict__ C, int M, int N, int K)
{
    extern __shared__ __align__(16) float smem[];
    float* Asm = smem;               // 2 stages of [128][36]
    float* Bsm = smem + 2 * ASZ;     // 2 stages of [32][136]

    const int tid  = threadIdx.x;
    const int lane = tid & 31;
    const int warp = tid >> 5;
    const int wm   = warp & 1;
    const int wn   = warp >> 1;
    const int m0   = blockIdx.y * 128;
    const int n0   = blockIdx.x * 128;
    const int lr   = lane >> 2;
    const int lc   = lane & 3;

    float acc[4][4][4];
#pragma unroll
    for (int i = 0; i < 4; i++)
#pragma unroll
        for (int j = 0; j < 4; j++)
#pragma unroll
            for (int v = 0; v < 4; v++) acc[i][j][v] = 0.f;

    // Precomputed staging indices
    const int ar  = (tid >> 3);          // base row pattern uses f = tid + i*256
    const int nk  = K >> 5;

    auto stage_load = [&](int s, int k0) {
        float* As = Asm + s * ASZ;
        float* Bs = Bsm + s * BSZ;
#pragma unroll
        for (int i = 0; i < 4; i++) {
            int f  = tid + i * 256;
            int r  = f >> 3;
            int c4 = f & 7;
            cpasync16(&As[r * AS_LD + c4 * 4],
                      &A[(size_t)(m0 + r) * K + k0 + c4 * 4], true);
        }
#pragma unroll
        for (int i = 0; i < 4; i++) {
            int f  = tid + i * 256;
            int kk = f >> 5;
            int c4 = f & 31;
            cpasync16(&Bs[kk * BS_LD + c4 * 4],
                      &B[(size_t)(k0 + kk) * N + n0 + c4 * 4],
                      (n0 + c4 * 4) < N);
        }
        asm volatile("cp.async.commit_group;\n");
    };
    (void)ar;

    stage_load(0, 0);

    for (int kt = 0; kt < nk; kt++) {
        asm volatile("cp.async.wait_group 0;\n");
        __syncthreads();
        if (kt + 1 < nk) stage_load((kt + 1) & 1, (kt + 1) * 32);

        const float* As = Asm + (kt & 1) * ASZ;
        const float* Bs = Bsm + (kt & 1) * BSZ;

#pragma unroll
        for (int ks = 0; ks < 32; ks += 8) {
            uint32_t af[4][4];
#pragma unroll
            for (int ma = 0; ma < 4; ma++) {
                int r = wm * 64 + ma * 16 + lr;
                af[ma][0] = f2tf32(As[r * AS_LD + ks + lc]);
                af[ma][1] = f2tf32(As[(r + 8) * AS_LD + ks + lc]);
                af[ma][2] = f2tf32(As[r * AS_LD + ks + 4 + lc]);
                af[ma][3] = f2tf32(As[(r + 8) * AS_LD + ks + 4 + lc]);
            }
            uint32_t bf[4][2];
#pragma unroll
            for (int na = 0; na < 4; na++) {
                int n = wn * 32 + na * 8 + lr;
                bf[na][0] = f2tf32(Bs[(ks + lc) * BS_LD + n]);
                bf[na][1] = f2tf32(Bs[(ks + 4 + lc) * BS_LD + n]);
            }
#pragma unroll
            for (int ma = 0; ma < 4; ma++)
#pragma unroll
                for (int na = 0; na < 4; na++) {
                    asm volatile(
                        "mma.sync.aligned.m16n8k8.row.col.f32.tf32.tf32.f32 "
                        "{%0,%1,%2,%3}, {%4,%5,%6,%7}, {%8,%9}, {%0,%1,%2,%3};\n"
                        : "+f"(acc[ma][na][0]), "+f"(acc[ma][na][1]),
                          "+f"(acc[ma][na][2]), "+f"(acc[ma][na][3])
                        : "r"(af[ma][0]), "r"(af[ma][1]), "r"(af[ma][2]), "r"(af[ma][3]),
                          "r"(bf[na][0]), "r"(bf[na][1]));
                }
        }
        __syncthreads();
    }

    // Epilogue
#pragma unroll
    for (int ma = 0; ma < 4; ma++) {
        int r0 = m0 + wm * 64 + ma * 16 + lr;
        int r1 = r0 + 8;
#pragma unroll
        for (int na = 0; na < 4; na++) {
            int c = n0 + wn * 32 + na * 8 + lc * 2;
            if (c < N) {
                float b0 = bias[c], b1 = bias[c + 1];
                float v00 = acc[ma][na][0] + b0;
                float v01 = acc[ma][na][1] + b1;
                float v10 = acc[ma][na][2] + b0;
                float v11 = acc[ma][na][3] + b1;
                if (resid) {
                    v00 += resid[(size_t)r0 * N + c];
                    v01 += resid[(size_t)r0 * N + c + 1];
                    v10 += resid[(size_t)r1 * N + c];
                    v11 += resid[(size_t)r1 * N + c + 1];
                }
                C[(size_t)r0 * N + c]     = v00;
                C[(size_t)r0 * N + c + 1] = v01;
                C[(size_t)r1 * N + c]     = v10;
                C[(size_t)r1 * N + c + 1] = v11;
            }
        }
    }
}

// ---------------------------------------------------------------------------
// Pack [W_off | W_attn] -> g_Wp (256x96), [b_off | b_attn] -> g_bp (96)
// ---------------------------------------------------------------------------
__global__ void pack_small(const float* __restrict__ W_off, const float* __restrict__ b_off,
                           const float* __restrict__ W_attn, const float* __restrict__ b_attn,
                           float* __restrict__ Wp, float* __restrict__ bp)
{
    int i = blockIdx.x * blockDim.x + threadIdx.x;
    int k = i / 96, n = i - k * 96;
    Wp[i] = (n < 64) ? W_off[k * 64 + n] : W_attn[k * 32 + (n - 64)];
    if (i < 96) bp[i] = (i < 64) ? b_off[i] : b_attn[i - 64];
}

// ---------------------------------------------------------------------------
// Deformable bilinear sampling + per-head softmax.
// Block = 256 threads = 4 rows. Per row: 64 threads, head = t>>3, 8 lanes per
// head each owning 4 channels (float4 gathers). Softmax/address math is
// amortized over 4 channels; aw folded into corner weights.
// ---------------------------------------------------------------------------
__global__ __launch_bounds__(256) void sample_kernel(
    const float* __restrict__ v, const float* __restrict__ offlg,
    float* __restrict__ out,
    const int* __restrict__ hptr, const int* __restrict__ wptr)
{
    const int h = *hptr, w = *wptr;
    const int HW = h * w;
    const int tid  = threadIdx.x;
    const int row  = blockIdx.x * 4 + (tid >> 6);
    const int t    = tid & 63;
    const int head = t >> 3;
    const int l8   = t & 7;

    const int b  = row / HW;
    const int q  = row - b * HW;
    const int qy = q / w;
    const int qx = q - qy * w;

    const float* base = offlg + row * 96;
    float4 lgv = *(const float4*)(base + 64 + head * 4);
    float4 o01 = *(const float4*)(base + head * 8);
    float4 o23 = *(const float4*)(base + head * 8 + 4);

    float mx = fmaxf(fmaxf(lgv.x, lgv.y), fmaxf(lgv.z, lgv.w));
    float e0 = __expf(lgv.x - mx), e1 = __expf(lgv.y - mx);
    float e2 = __expf(lgv.z - mx), e3 = __expf(lgv.w - mx);
    float inv = 1.f / (e0 + e1 + e2 + e3);
    float aw[PTS] = {e0 * inv, e1 * inv, e2 * inv, e3 * inv};
    float ofx[PTS] = {o01.x, o01.z, o23.x, o23.z};
    float ofy[PTS] = {o01.y, o01.w, o23.y, o23.w};

    const float* vb = v + ((b * HW) << 8) + head * 32 + l8 * 4;
    const int wst = w << 8;

    float4 acc = make_float4(0.f, 0.f, 0.f, 0.f);
#pragma unroll
    for (int p = 0; p < PTS; p++) {
        float ix = (float)qx + ofx[p];
        float iy = (float)qy + ofy[p];
        float xf = floorf(ix), yf = floorf(iy);
        int x0 = (int)xf, y0 = (int)yf;
        float wx1 = ix - xf, wy1 = iy - yf;
        float wx0 = 1.f - wx1, wy0 = 1.f - wy1;

        bool vx0 = (unsigned)x0 < (unsigned)w;
        bool vx1 = (unsigned)(x0 + 1) < (unsigned)w;
        bool vy0 = (unsigned)y0 < (unsigned)h;
        bool vy1 = (unsigned)(y0 + 1) < (unsigned)h;

        float w00 = wx0 * wy0 * aw[p];
        float w01 = wx1 * wy0 * aw[p];
        float w10 = wx0 * wy1 * aw[p];
        float w11 = wx1 * wy1 * aw[p];

        int o00 = (y0 * w + x0) << 8;
        if (vy0 && vx0) {
            float4 c = *(const float4*)(vb + o00);
            acc.x = fmaf(w00, c.x, acc.x); acc.y = fmaf(w00, c.y, acc.y);
            acc.z = fmaf(w00, c.z, acc.z); acc.w = fmaf(w00, c.w, acc.w);
        }
        if (vy0 && vx1) {
            float4 c = *(const float4*)(vb + o00 + 256);
            acc.x = fmaf(w01, c.x, acc.x); acc.y = fmaf(w01, c.y, acc.y);
            acc.z = fmaf(w01, c.z, acc.z); acc.w = fmaf(w01, c.w, acc.w);
        }
        if (vy1 && vx0) {
            float4 c = *(const float4*)(vb + o00 + wst);
            acc.x = fmaf(w10, c.x, acc.x); acc.y = fmaf(w10, c.y, acc.y);
            acc.z = fmaf(w10, c.z, acc.z); acc.w = fmaf(w10, c.w, acc.w);
        }
        if (vy1 && vx1) {
            float4 c = *(const float4*)(vb + o00 + wst + 256);
            acc.x = fmaf(w11, c.x, acc.x); acc.y = fmaf(w11, c.y, acc.y);
            acc.z = fmaf(w11, c.z, acc.z); acc.w = fmaf(w11, c.w, acc.w);
        }
    }
    *(float4*)(out + (row << 8) + head * 32 + l8 * 4) = acc;
}

// ---------------------------------------------------------------------------

extern "C" void kernel_launch(void* const* d_in, const int* in_sizes, int n_in,
                              void* d_out, int out_size)
{
    const float* query  = (const float*)d_in[0];
    const float* value  = (const float*)d_in[1];
    const float* W_off  = (const float*)d_in[2];
    const float* b_off  = (const float*)d_in[3];
    const float* W_attn = (const float*)d_in[4];
    const float* b_attn = (const float*)d_in[5];
    const float* W_val  = (const float*)d_in[6];
    const float* b_val  = (const float*)d_in[7];
    const float* W_out  = (const float*)d_in[8];
    const float* b_out  = (const float*)d_in[9];
    const int*   hp     = (const int*)d_in[10];
    const int*   wp     = (const int*)d_in[11];
    float* out = (float*)d_out;

    const int K = in_sizes[2] / (HEADS * PTS * 2);   // 256
    const int M = in_sizes[0] / K;                   // 32768
    const int N = in_sizes[6] / K;                   // 256

    float *gv, *gofflg, *gattn, *gWp, *gbp;
    cudaGetSymbolAddress((void**)&gv,     g_v);
    cudaGetSymbolAddress((void**)&gofflg, g_offlg);
    cudaGetSymbolAddress((void**)&gattn,  g_attn);
    cudaGetSymbolAddress((void**)&gWp,    g_Wp);
    cudaGetSymbolAddress((void**)&gbp,    g_bp);

    cudaFuncSetAttribute(gemm_tf32, cudaFuncAttributeMaxDynamicSharedMemorySize, GEMM_SMEM);

    // 0. pack small weights [W_off | W_attn]
    pack_small<<<(K * 96) / 256, 256>>>(W_off, b_off, W_attn, b_attn, gWp, gbp);
    // 1. v = value @ W_val + b_val
    gemm_tf32<<<dim3((N + 127) / 128, M / 128), 256, GEMM_SMEM>>>(value, W_val, b_val, nullptr, gv, M, N, K);
    // 2+3. [off | logits] = query @ [W_off | W_attn] + bias
    gemm_tf32<<<dim3(1, M / 128), 256, GEMM_SMEM>>>(query, gWp, gbp, nullptr, gofflg, M, 96, K);
    // 4. deformable sampling (+ per-head softmax over points)
    sample_kernel<<<M / 4, 256>>>(gv, gofflg, gattn, hp, wp);
    // 5. out = attn @ W_out + b_out + query
    gemm_tf32<<<dim3((N + 127) / 128, M / 128), 256, GEMM_SMEM>>>(gattn, W_out, b_out, query, out, M, N, K);
}

// round 4
// speedup vs baseline: 2.7414x; 1.1232x over previous
#include <cuda_runtime.h>
#include <cuda_bf16.h>
#include <math.h>
#include <stdint.h>

#define HEADS   8
#define PTS     4
#define CH      256
#define MAXROWS 32768

// Scratch (__device__ globals per allocation-free rule)
__device__ float g_v[MAXROWS * CH];                 // value @ W_val
__device__ float g_offlg[MAXROWS * 96];             // [off(64) | logits(32)] per row
__device__ float g_attn[MAXROWS * CH];              // sampled output
__device__ float g_Wp[CH * 96];                     // packed [W_off | W_attn]
__device__ float g_bp[96];

// Streams/events for fork-join inside graph capture (created before capture).
static cudaStream_t s_side = nullptr;
static cudaEvent_t  e_fork = nullptr, e_join = nullptr;
namespace {
struct StreamInit {
    StreamInit() {
        cudaStreamCreateWithFlags(&s_side, cudaStreamNonBlocking);
        cudaEventCreateWithFlags(&e_fork, cudaEventDisableTiming);
        cudaEventCreateWithFlags(&e_join, cudaEventDisableTiming);
    }
} s_init;
}

// ---------------------------------------------------------------------------
// tf32 tensor-core GEMM, cp.async double-buffered, software-pipelined frags.
// C[M,N] = A[M,K] @ B[K,N] + bias[N] (+ resid)
// Block tile 128x128x32, 256 thr = 8 warps (2m x 4n), warp tile 64x32.
// ---------------------------------------------------------------------------
__device__ __forceinline__ uint32_t f2tf32(float x) {
    uint32_t r;
    asm("cvt.rna.tf32.f32 %0, %1;" : "=r"(r) : "f"(x));
    return r;
}

__device__ __forceinline__ void cpasync16(float* dst_smem, const float* src, bool pred) {
    uint32_t d = (uint32_t)__cvta_generic_to_shared(dst_smem);
    int sz = pred ? 16 : 0;
    asm volatile("cp.async.cg.shared.global [%0], [%1], 16, %2;\n"
                 :: "r"(d), "l"(src), "r"(sz));
}

#define AS_LD 36
#define BS_LD 136
#define ASZ (128 * AS_LD)
#define BSZ (32 * BS_LD)
#define GEMM_SMEM ((2 * ASZ + 2 * BSZ) * 4)

__global__ __launch_bounds__(256) void gemm_tf32(
    const float* __restrict__ A, const float* __restrict__ B,
    const float* __restrict__ bias, const float* __restrict__ resid,
    float* __restrict__ C, int M, int N, int K)
{
    extern __shared__ __align__(16) float smem[];
    float* Asm = smem;
    float* Bsm = smem + 2 * ASZ;

    const int tid  = threadIdx.x;
    const int lane = tid & 31;
    const int warp = tid >> 5;
    const int wm   = warp & 1;
    const int wn   = warp >> 1;
    const int m0   = blockIdx.y * 128;
    const int n0   = blockIdx.x * 128;
    const int lr   = lane >> 2;
    const int lc   = lane & 3;

    float acc[4][4][4];
#pragma unroll
    for (int i = 0; i < 4; i++)
#pragma unroll
        for (int j = 0; j < 4; j++)
#pragma unroll
            for (int v = 0; v < 4; v++) acc[i][j][v] = 0.f;

    const int nk = K >> 5;

    auto stage_load = [&](int s, int k0) {
        float* As = Asm + s * ASZ;
        float* Bs = Bsm + s * BSZ;
#pragma unroll
        for (int i = 0; i < 4; i++) {
            int f  = tid + i * 256;
            int r  = f >> 3;
            int c4 = f & 7;
            cpasync16(&As[r * AS_LD + c4 * 4],
                      &A[(size_t)(m0 + r) * K + k0 + c4 * 4], true);
        }
#pragma unroll
        for (int i = 0; i < 4; i++) {
            int f  = tid + i * 256;
            int kk = f >> 5;
            int c4 = f & 31;
            cpasync16(&Bs[kk * BS_LD + c4 * 4],
                      &B[(size_t)(k0 + kk) * N + n0 + c4 * 4],
                      (n0 + c4 * 4) < N);
        }
        asm volatile("cp.async.commit_group;\n");
    };

    stage_load(0, 0);

    uint32_t af[2][4][4];
    uint32_t bf[2][4][2];

    for (int kt = 0; kt < nk; kt++) {
        asm volatile("cp.async.wait_group 0;\n");
        __syncthreads();
        if (kt + 1 < nk) stage_load((kt + 1) & 1, (kt + 1) * 32);

        const float* As = Asm + (kt & 1) * ASZ;
        const float* Bs = Bsm + (kt & 1) * BSZ;

        // Load fragments for ks=0 into buffer 0
#pragma unroll
        for (int ma = 0; ma < 4; ma++) {
            int r = wm * 64 + ma * 16 + lr;
            af[0][ma][0] = f2tf32(As[r * AS_LD + lc]);
            af[0][ma][1] = f2tf32(As[(r + 8) * AS_LD + lc]);
            af[0][ma][2] = f2tf32(As[r * AS_LD + 4 + lc]);
            af[0][ma][3] = f2tf32(As[(r + 8) * AS_LD + 4 + lc]);
        }
#pragma unroll
        for (int na = 0; na < 4; na++) {
            int n = wn * 32 + na * 8 + lr;
            bf[0][na][0] = f2tf32(Bs[lc * BS_LD + n]);
            bf[0][na][1] = f2tf32(Bs[(4 + lc) * BS_LD + n]);
        }

#pragma unroll
        for (int s = 0; s < 4; s++) {
            int cur = s & 1, nxt = cur ^ 1;
            if (s < 3) {
                int ks = (s + 1) * 8;
#pragma unroll
                for (int ma = 0; ma < 4; ma++) {
                    int r = wm * 64 + ma * 16 + lr;
                    af[nxt][ma][0] = f2tf32(As[r * AS_LD + ks + lc]);
                    af[nxt][ma][1] = f2tf32(As[(r + 8) * AS_LD + ks + lc]);
                    af[nxt][ma][2] = f2tf32(As[r * AS_LD + ks + 4 + lc]);
                    af[nxt][ma][3] = f2tf32(As[(r + 8) * AS_LD + ks + 4 + lc]);
                }
#pragma unroll
                for (int na = 0; na < 4; na++) {
                    int n = wn * 32 + na * 8 + lr;
                    bf[nxt][na][0] = f2tf32(Bs[(ks + lc) * BS_LD + n]);
                    bf[nxt][na][1] = f2tf32(Bs[(ks + 4 + lc) * BS_LD + n]);
                }
            }
#pragma unroll
            for (int ma = 0; ma < 4; ma++)
#pragma unroll
                for (int na = 0; na < 4; na++) {
                    asm volatile(
                        "mma.sync.aligned.m16n8k8.row.col.f32.tf32.tf32.f32 "
                        "{%0,%1,%2,%3}, {%4,%5,%6,%7}, {%8,%9}, {%0,%1,%2,%3};\n"
                        : "+f"(acc[ma][na][0]), "+f"(acc[ma][na][1]),
                          "+f"(acc[ma][na][2]), "+f"(acc[ma][na][3])
                        : "r"(af[cur][ma][0]), "r"(af[cur][ma][1]),
                          "r"(af[cur][ma][2]), "r"(af[cur][ma][3]),
                          "r"(bf[cur][na][0]), "r"(bf[cur][na][1]));
                }
        }
        __syncthreads();
    }

    // Epilogue (float2-vectorized)
#pragma unroll
    for (int ma = 0; ma < 4; ma++) {
        int r0 = m0 + wm * 64 + ma * 16 + lr;
        int r1 = r0 + 8;
#pragma unroll
        for (int na = 0; na < 4; na++) {
            int c = n0 + wn * 32 + na * 8 + lc * 2;
            if (c < N) {
                float2 bv = *(const float2*)&bias[c];
                float2 v0 = make_float2(acc[ma][na][0] + bv.x, acc[ma][na][1] + bv.y);
                float2 v1 = make_float2(acc[ma][na][2] + bv.x, acc[ma][na][3] + bv.y);
                if (resid) {
                    float2 r0v = *(const float2*)&resid[(size_t)r0 * N + c];
                    float2 r1v = *(const float2*)&resid[(size_t)r1 * N + c];
                    v0.x += r0v.x; v0.y += r0v.y;
                    v1.x += r1v.x; v1.y += r1v.y;
                }
                *(float2*)&C[(size_t)r0 * N + c] = v0;
                *(float2*)&C[(size_t)r1 * N + c] = v1;
            }
        }
    }
}

// ---------------------------------------------------------------------------
__global__ void pack_small(const float* __restrict__ W_off, const float* __restrict__ b_off,
                           const float* __restrict__ W_attn, const float* __restrict__ b_attn,
                           float* __restrict__ Wp, float* __restrict__ bp)
{
    int i = blockIdx.x * blockDim.x + threadIdx.x;
    int k = i / 96, n = i - k * 96;
    Wp[i] = (n < 64) ? W_off[k * 64 + n] : W_attn[k * 32 + (n - 64)];
    if (i < 96) bp[i] = (i < 64) ? b_off[i] : b_attn[i - 64];
}

// ---------------------------------------------------------------------------
// Deformable bilinear sampling + per-head softmax.
// Block = 256 threads = 4 rows; 8 lanes per head, float4 channels.
// min 5 blocks/SM -> caps regs at 51 (was 52), occ 44% -> 62%.
// ---------------------------------------------------------------------------
__global__ __launch_bounds__(256, 5) void sample_kernel(
    const float* __restrict__ v, const float* __restrict__ offlg,
    float* __restrict__ out,
    const int* __restrict__ hptr, const int* __restrict__ wptr)
{
    const int h = *hptr, w = *wptr;
    const int HW = h * w;
    const int tid  = threadIdx.x;
    const int row  = blockIdx.x * 4 + (tid >> 6);
    const int t    = tid & 63;
    const int head = t >> 3;
    const int l8   = t & 7;

    const int b  = row / HW;
    const int q  = row - b * HW;
    const int qy = q / w;
    const int qx = q - qy * w;

    const float* base = offlg + row * 96;
    float4 lgv = *(const float4*)(base + 64 + head * 4);
    float4 o01 = *(const float4*)(base + head * 8);
    float4 o23 = *(const float4*)(base + head * 8 + 4);

    float mx = fmaxf(fmaxf(lgv.x, lgv.y), fmaxf(lgv.z, lgv.w));
    float e0 = __expf(lgv.x - mx), e1 = __expf(lgv.y - mx);
    float e2 = __expf(lgv.z - mx), e3 = __expf(lgv.w - mx);
    float inv = 1.f / (e0 + e1 + e2 + e3);
    float aw[PTS] = {e0 * inv, e1 * inv, e2 * inv, e3 * inv};
    float ofx[PTS] = {o01.x, o01.z, o23.x, o23.z};
    float ofy[PTS] = {o01.y, o01.w, o23.y, o23.w};

    const float* vb = v + ((b * HW) << 8) + head * 32 + l8 * 4;
    const int wst = w << 8;

    float4 acc = make_float4(0.f, 0.f, 0.f, 0.f);
#pragma unroll
    for (int p = 0; p < PTS; p++) {
        float ix = (float)qx + ofx[p];
        float iy = (float)qy + ofy[p];
        float xf = floorf(ix), yf = floorf(iy);
        int x0 = (int)xf, y0 = (int)yf;
        float wx1 = ix - xf, wy1 = iy - yf;
        float wx0 = 1.f - wx1, wy0 = 1.f - wy1;

        bool vx0 = (unsigned)x0 < (unsigned)w;
        bool vx1 = (unsigned)(x0 + 1) < (unsigned)w;
        bool vy0 = (unsigned)y0 < (unsigned)h;
        bool vy1 = (unsigned)(y0 + 1) < (unsigned)h;

        float w00 = wx0 * wy0 * aw[p];
        float w01 = wx1 * wy0 * aw[p];
        float w10 = wx0 * wy1 * aw[p];
        float w11 = wx1 * wy1 * aw[p];

        int o00 = (y0 * w + x0) << 8;
        if (vy0 && vx0) {
            float4 c = *(const float4*)(vb + o00);
            acc.x = fmaf(w00, c.x, acc.x); acc.y = fmaf(w00, c.y, acc.y);
            acc.z = fmaf(w00, c.z, acc.z); acc.w = fmaf(w00, c.w, acc.w);
        }
        if (vy0 && vx1) {
            float4 c = *(const float4*)(vb + o00 + 256);
            acc.x = fmaf(w01, c.x, acc.x); acc.y = fmaf(w01, c.y, acc.y);
            acc.z = fmaf(w01, c.z, acc.z); acc.w = fmaf(w01, c.w, acc.w);
        }
        if (vy1 && vx0) {
            float4 c = *(const float4*)(vb + o00 + wst);
            acc.x = fmaf(w10, c.x, acc.x); acc.y = fmaf(w10, c.y, acc.y);
            acc.z = fmaf(w10, c.z, acc.z); acc.w = fmaf(w10, c.w, acc.w);
        }
        if (vy1 && vx1) {
            float4 c = *(const float4*)(vb + o00 + wst + 256);
            acc.x = fmaf(w11, c.x, acc.x); acc.y = fmaf(w11, c.y, acc.y);
            acc.z = fmaf(w11, c.z, acc.z); acc.w = fmaf(w11, c.w, acc.w);
        }
    }
    *(float4*)(out + (row << 8) + head * 32 + l8 * 4) = acc;
}

// ---------------------------------------------------------------------------

extern "C" void kernel_launch(void* const* d_in, const int* in_sizes, int n_in,
                              void* d_out, int out_size)
{
    const float* query  = (const float*)d_in[0];
    const float* value  = (const float*)d_in[1];
    const float* W_off  = (const float*)d_in[2];
    const float* b_off  = (const float*)d_in[3];
    const float* W_attn = (const float*)d_in[4];
    const float* b_attn = (const float*)d_in[5];
    const float* W_val  = (const float*)d_in[6];
    const float* b_val  = (const float*)d_in[7];
    const float* W_out  = (const float*)d_in[8];
    const float* b_out  = (const float*)d_in[9];
    const int*   hp     = (const int*)d_in[10];
    const int*   wp     = (const int*)d_in[11];
    float* out = (float*)d_out;

    const int K = in_sizes[2] / (HEADS * PTS * 2);   // 256
    const int M = in_sizes[0] / K;                   // 32768
    const int N = in_sizes[6] / K;                   // 256

    float *gv, *gofflg, *gattn, *gWp, *gbp;
    cudaGetSymbolAddress((void**)&gv,     g_v);
    cudaGetSymbolAddress((void**)&gofflg, g_offlg);
    cudaGetSymbolAddress((void**)&gattn,  g_attn);
    cudaGetSymbolAddress((void**)&gWp,    g_Wp);
    cudaGetSymbolAddress((void**)&gbp,    g_bp);

    cudaFuncSetAttribute(gemm_tf32, cudaFuncAttributeMaxDynamicSharedMemorySize, GEMM_SMEM);

    // Fork: value path (GEMM1) on side stream, query path on main stream.
    cudaEventRecord(e_fork, 0);
    cudaStreamWaitEvent(s_side, e_fork, 0);

    // side: v = value @ W_val + b_val
    gemm_tf32<<<dim3((N + 127) / 128, M / 128), 256, GEMM_SMEM, s_side>>>(
        value, W_val, b_val, nullptr, gv, M, N, K);
    cudaEventRecord(e_join, s_side);

    // main: pack + [off|logits] = query @ [W_off|W_attn] + bias
    pack_small<<<(K * 96) / 256, 256>>>(W_off, b_off, W_attn, b_attn, gWp, gbp);
    gemm_tf32<<<dim3(1, M / 128), 256, GEMM_SMEM>>>(query, gWp, gbp, nullptr, gofflg, M, 96, K);

    // join, then sampling + output GEMM
    cudaStreamWaitEvent(0, e_join, 0);
    sample_kernel<<<M / 4, 256>>>(gv, gofflg, gattn, hp, wp);
    gemm_tf32<<<dim3((N + 127) / 128, M / 128), 256, GEMM_SMEM>>>(
        gattn, W_out, b_out, query, out, M, N, K);
}

// round 5
// speedup vs baseline: 3.2520x; 1.1862x over previous
#include <cuda_runtime.h>
#include <cuda_bf16.h>
#include <math.h>
#include <stdint.h>

#define HEADS   8
#define PTS     4
#define CH      256
#define MAXROWS 32768

// Scratch (__device__ globals per allocation-free rule)
__device__ float    g_v[MAXROWS * CH];          // value @ W_val (fp32)
__device__ float    g_offlg[MAXROWS * 96];      // [off(64) | logits(32)] per row
__device__ uint32_t g_attnb[MAXROWS * CH / 2];  // sampled output, packed bf16x2
__device__ float    g_Wp[CH * 96];              // packed fp32 [W_off | W_attn]
__device__ float    g_bp[96];
__device__ uint32_t g_Wvalp[CH * CH / 2];       // bf16x2-packed weights
__device__ uint32_t g_Woutp[CH * CH / 2];

// Streams/events for fork-join inside graph capture (created before capture).
static cudaStream_t s_side = nullptr;
static cudaEvent_t  e_fork = nullptr, e_join = nullptr;
namespace {
struct StreamInit {
    StreamInit() {
        cudaStreamCreateWithFlags(&s_side, cudaStreamNonBlocking);
        cudaEventCreateWithFlags(&e_fork, cudaEventDisableTiming);
        cudaEventCreateWithFlags(&e_join, cudaEventDisableTiming);
    }
} s_init;
}

__device__ __forceinline__ uint32_t f2tf32(float x) {
    uint32_t r;
    asm("cvt.rna.tf32.f32 %0, %1;" : "=r"(r) : "f"(x));
    return r;
}
// pack2(lo, hi): lo -> bits[0:16), hi -> bits[16:32)
__device__ __forceinline__ uint32_t pack2(float lo, float hi) {
    uint32_t r;
    asm("cvt.rn.bf16x2.f32 %0, %1, %2;" : "=r"(r) : "f"(hi), "f"(lo));
    return r;
}
__device__ __forceinline__ void cpasync16(void* dst_smem, const void* src, bool pred) {
    uint32_t d = (uint32_t)__cvta_generic_to_shared(dst_smem);
    int sz = pred ? 16 : 0;
    asm volatile("cp.async.cg.shared.global [%0], [%1], 16, %2;\n"
                 :: "r"(d), "l"(src), "r"(sz));
}

// ===========================================================================
// bf16 tensor-core GEMM (m16n8k16), cp.async double-buffered.
// C[M,N](fp32) = A[M,K] @ B[K,N] + bias (+ resid). B pre-packed bf16x2 [K/2][N].
// A: fp32 (convert at frag read) if !ABF16, else bf16 row-major.
// Block 128x128x32, 8 warps (2m x 4n), warp tile 64x32.
// ===========================================================================
#define ALD_F 40            // fp32 A row pad (words)
#define ALD_H 20            // bf16 A row pad (words; 32 bf16 = 16 words + 4)
#define BLD   136           // B row pad (words; 128 + 8)
#define ASZ_F (128 * ALD_F)
#define ASZ_H (128 * ALD_H)
#define BSZP  (16 * BLD)
#define SMEM_GF ((2 * ASZ_F + 2 * BSZP) * 4)
#define SMEM_GH ((2 * ASZ_H + 2 * BSZP) * 4)

template<bool ABF16>
__global__ __launch_bounds__(256) void gemm_bf16(
    const void* __restrict__ Av, const uint32_t* __restrict__ Bp,
    const float* __restrict__ bias, const float* __restrict__ resid,
    float* __restrict__ C, int M, int N, int K)
{
    extern __shared__ __align__(16) uint32_t smemw[];
    const int ASZ = ABF16 ? ASZ_H : ASZ_F;
    uint32_t* Asm = smemw;
    uint32_t* Bsm = smemw + 2 * ASZ;

    const int tid  = threadIdx.x;
    const int lane = tid & 31;
    const int warp = tid >> 5;
    const int wm   = warp & 1;
    const int wn   = warp >> 1;
    const int m0   = blockIdx.y * 128;
    const int n0   = blockIdx.x * 128;
    const int lr   = lane >> 2;
    const int lc   = lane & 3;

    float acc[4][4][4];
#pragma unroll
    for (int i = 0; i < 4; i++)
#pragma unroll
        for (int j = 0; j < 4; j++)
#pragma unroll
            for (int v = 0; v < 4; v++) acc[i][j][v] = 0.f;

    const int nk = K >> 5;

    auto stage_load = [&](int s, int k0) {
        uint32_t* As = Asm + s * ASZ;
        uint32_t* Bs = Bsm + s * BSZP;
        if (ABF16) {
            const __nv_bfloat16* A = (const __nv_bfloat16*)Av;
#pragma unroll
            for (int i = 0; i < 2; i++) {
                int f = tid + i * 256;
                int r = f >> 2, c = f & 3;
                cpasync16(&As[r * ALD_H + c * 4],
                          &A[(size_t)(m0 + r) * K + k0 + c * 8], true);
            }
        } else {
            const float* A = (const float*)Av;
#pragma unroll
            for (int i = 0; i < 4; i++) {
                int f = tid + i * 256;
                int r = f >> 3, c4 = f & 7;
                cpasync16(&As[r * ALD_F + c4 * 4],
                          &A[(size_t)(m0 + r) * K + k0 + c4 * 4], true);
            }
        }
#pragma unroll
        for (int i = 0; i < 2; i++) {
            int f  = tid + i * 256;
            int kp = f >> 5;
            int c4 = f & 31;
            int n  = n0 + c4 * 4;
            cpasync16(&Bs[kp * BLD + c4 * 4],
                      &Bp[(size_t)((k0 >> 1) + kp) * N + n], n < N);
        }
        asm volatile("cp.async.commit_group;\n");
    };

    stage_load(0, 0);

    uint32_t af[2][4][4];
    uint32_t bf[2][4][2];

    auto frag_load = [&](const uint32_t* As, const uint32_t* Bs, int buf, int ks) {
#pragma unroll
        for (int ma = 0; ma < 4; ma++) {
            int r = wm * 64 + ma * 16 + lr;
            if (ABF16) {
                af[buf][ma][0] = As[r * ALD_H + (ks >> 1) + lc];
                af[buf][ma][1] = As[(r + 8) * ALD_H + (ks >> 1) + lc];
                af[buf][ma][2] = As[r * ALD_H + (ks >> 1) + 4 + lc];
                af[buf][ma][3] = As[(r + 8) * ALD_H + (ks >> 1) + 4 + lc];
            } else {
                const float* Af = (const float*)As;
                float2 a0 = *(const float2*)&Af[r * ALD_F + ks + 2 * lc];
                float2 a1 = *(const float2*)&Af[(r + 8) * ALD_F + ks + 2 * lc];
                float2 a2 = *(const float2*)&Af[r * ALD_F + ks + 8 + 2 * lc];
                float2 a3 = *(const float2*)&Af[(r + 8) * ALD_F + ks + 8 + 2 * lc];
                af[buf][ma][0] = pack2(a0.x, a0.y);
                af[buf][ma][1] = pack2(a1.x, a1.y);
                af[buf][ma][2] = pack2(a2.x, a2.y);
                af[buf][ma][3] = pack2(a3.x, a3.y);
            }
        }
#pragma unroll
        for (int na = 0; na < 4; na++) {
            int n = wn * 32 + na * 8 + lr;
            bf[buf][na][0] = Bs[((ks >> 1) + lc) * BLD + n];
            bf[buf][na][1] = Bs[((ks >> 1) + 4 + lc) * BLD + n];
        }
    };

    for (int kt = 0; kt < nk; kt++) {
        asm volatile("cp.async.wait_group 0;\n");
        __syncthreads();
        if (kt + 1 < nk) stage_load((kt + 1) & 1, (kt + 1) * 32);

        const uint32_t* As = Asm + (kt & 1) * ASZ;
        const uint32_t* Bs = Bsm + (kt & 1) * BSZP;

        frag_load(As, Bs, 0, 0);
#pragma unroll
        for (int s = 0; s < 2; s++) {
            int cur = s & 1, nxt = cur ^ 1;
            if (s == 0) frag_load(As, Bs, nxt, 16);
#pragma unroll
            for (int ma = 0; ma < 4; ma++)
#pragma unroll
                for (int na = 0; na < 4; na++) {
                    asm volatile(
                        "mma.sync.aligned.m16n8k16.row.col.f32.bf16.bf16.f32 "
                        "{%0,%1,%2,%3}, {%4,%5,%6,%7}, {%8,%9}, {%0,%1,%2,%3};\n"
                        : "+f"(acc[ma][na][0]), "+f"(acc[ma][na][1]),
                          "+f"(acc[ma][na][2]), "+f"(acc[ma][na][3])
                        : "r"(af[cur][ma][0]), "r"(af[cur][ma][1]),
                          "r"(af[cur][ma][2]), "r"(af[cur][ma][3]),
                          "r"(bf[cur][na][0]), "r"(bf[cur][na][1]));
                }
        }
        __syncthreads();
    }

#pragma unroll
    for (int ma = 0; ma < 4; ma++) {
        int r0 = m0 + wm * 64 + ma * 16 + lr;
        int r1 = r0 + 8;
#pragma unroll
        for (int na = 0; na < 4; na++) {
            int c = n0 + wn * 32 + na * 8 + lc * 2;
            if (c < N) {
                float2 bv = *(const float2*)&bias[c];
                float2 v0 = make_float2(acc[ma][na][0] + bv.x, acc[ma][na][1] + bv.y);
                float2 v1 = make_float2(acc[ma][na][2] + bv.x, acc[ma][na][3] + bv.y);
                if (resid) {
                    float2 r0v = *(const float2*)&resid[(size_t)r0 * N + c];
                    float2 r1v = *(const float2*)&resid[(size_t)r1 * N + c];
                    v0.x += r0v.x; v0.y += r0v.y;
                    v1.x += r1v.x; v1.y += r1v.y;
                }
                *(float2*)&C[(size_t)r0 * N + c] = v0;
                *(float2*)&C[(size_t)r1 * N + c] = v1;
            }
        }
    }
}

// ===========================================================================
// tf32 GEMM (kept for the small offsets/logits GEMM — error-sensitive path)
// ===========================================================================
#define AS_LD 36
#define BS_LD 136
#define ASZ32 (128 * AS_LD)
#define BSZ32 (32 * BS_LD)
#define GEMM_SMEM ((2 * ASZ32 + 2 * BSZ32) * 4)

__global__ __launch_bounds__(256) void gemm_tf32(
    const float* __restrict__ A, const float* __restrict__ B,
    const float* __restrict__ bias, const float* __restrict__ resid,
    float* __restrict__ C, int M, int N, int K)
{
    extern __shared__ __align__(16) float smem[];
    float* Asm = smem;
    float* Bsm = smem + 2 * ASZ32;

    const int tid  = threadIdx.x;
    const int lane = tid & 31;
    const int warp = tid >> 5;
    const int wm   = warp & 1;
    const int wn   = warp >> 1;
    const int m0   = blockIdx.y * 128;
    const int n0   = blockIdx.x * 128;
    const int lr   = lane >> 2;
    const int lc   = lane & 3;

    float acc[4][4][4];
#pragma unroll
    for (int i = 0; i < 4; i++)
#pragma unroll
        for (int j = 0; j < 4; j++)
#pragma unroll
            for (int v = 0; v < 4; v++) acc[i][j][v] = 0.f;

    const int nk = K >> 5;

    auto stage_load = [&](int s, int k0) {
        float* As = Asm + s * ASZ32;
        float* Bs = Bsm + s * BSZ32;
#pragma unroll
        for (int i = 0; i < 4; i++) {
            int f  = tid + i * 256;
            int r  = f >> 3;
            int c4 = f & 7;
            cpasync16(&As[r * AS_LD + c4 * 4],
                      &A[(size_t)(m0 + r) * K + k0 + c4 * 4], true);
        }
#pragma unroll
        for (int i = 0; i < 4; i++) {
            int f  = tid + i * 256;
            int kk = f >> 5;
            int c4 = f & 31;
            cpasync16(&Bs[kk * BS_LD + c4 * 4],
                      &B[(size_t)(k0 + kk) * N + n0 + c4 * 4],
                      (n0 + c4 * 4) < N);
        }
        asm volatile("cp.async.commit_group;\n");
    };

    stage_load(0, 0);

    uint32_t af[2][4][4];
    uint32_t bf[2][4][2];

    for (int kt = 0; kt < nk; kt++) {
        asm volatile("cp.async.wait_group 0;\n");
        __syncthreads();
        if (kt + 1 < nk) stage_load((kt + 1) & 1, (kt + 1) * 32);

        const float* As = Asm + (kt & 1) * ASZ32;
        const float* Bs = Bsm + (kt & 1) * BSZ32;

#pragma unroll
        for (int ma = 0; ma < 4; ma++) {
            int r = wm * 64 + ma * 16 + lr;
            af[0][ma][0] = f2tf32(As[r * AS_LD + lc]);
            af[0][ma][1] = f2tf32(As[(r + 8) * AS_LD + lc]);
            af[0][ma][2] = f2tf32(As[r * AS_LD + 4 + lc]);
            af[0][ma][3] = f2tf32(As[(r + 8) * AS_LD + 4 + lc]);
        }
#pragma unroll
        for (int na = 0; na < 4; na++) {
            int n = wn * 32 + na * 8 + lr;
            bf[0][na][0] = f2tf32(Bs[lc * BS_LD + n]);
            bf[0][na][1] = f2tf32(Bs[(4 + lc) * BS_LD + n]);
        }

#pragma unroll
        for (int s = 0; s < 4; s++) {
            int cur = s & 1, nxt = cur ^ 1;
            if (s < 3) {
                int ks = (s + 1) * 8;
#pragma unroll
                for (int ma = 0; ma < 4; ma++) {
                    int r = wm * 64 + ma * 16 + lr;
                    af[nxt][ma][0] = f2tf32(As[r * AS_LD + ks + lc]);
                    af[nxt][ma][1] = f2tf32(As[(r + 8) * AS_LD + ks + lc]);
                    af[nxt][ma][2] = f2tf32(As[r * AS_LD + ks + 4 + lc]);
                    af[nxt][ma][3] = f2tf32(As[(r + 8) * AS_LD + ks + 4 + lc]);
                }
#pragma unroll
                for (int na = 0; na < 4; na++) {
                    int n = wn * 32 + na * 8 + lr;
                    bf[nxt][na][0] = f2tf32(Bs[(ks + lc) * BS_LD + n]);
                    bf[nxt][na][1] = f2tf32(Bs[(ks + 4 + lc) * BS_LD + n]);
                }
            }
#pragma unroll
            for (int ma = 0; ma < 4; ma++)
#pragma unroll
                for (int na = 0; na < 4; na++) {
                    asm volatile(
                        "mma.sync.aligned.m16n8k8.row.col.f32.tf32.tf32.f32 "
                        "{%0,%1,%2,%3}, {%4,%5,%6,%7}, {%8,%9}, {%0,%1,%2,%3};\n"
                        : "+f"(acc[ma][na][0]), "+f"(acc[ma][na][1]),
                          "+f"(acc[ma][na][2]), "+f"(acc[ma][na][3])
                        : "r"(af[cur][ma][0]), "r"(af[cur][ma][1]),
                          "r"(af[cur][ma][2]), "r"(af[cur][ma][3]),
                          "r"(bf[cur][na][0]), "r"(bf[cur][na][1]));
                }
        }
        __syncthreads();
    }

#pragma unroll
    for (int ma = 0; ma < 4; ma++) {
        int r0 = m0 + wm * 64 + ma * 16 + lr;
        int r1 = r0 + 8;
#pragma unroll
        for (int na = 0; na < 4; na++) {
            int c = n0 + wn * 32 + na * 8 + lc * 2;
            if (c < N) {
                float2 bv = *(const float2*)&bias[c];
                float2 v0 = make_float2(acc[ma][na][0] + bv.x, acc[ma][na][1] + bv.y);
                float2 v1 = make_float2(acc[ma][na][2] + bv.x, acc[ma][na][3] + bv.y);
                if (resid) {
                    float2 r0v = *(const float2*)&resid[(size_t)r0 * N + c];
                    float2 r1v = *(const float2*)&resid[(size_t)r1 * N + c];
                    v0.x += r0v.x; v0.y += r0v.y;
                    v1.x += r1v.x; v1.y += r1v.y;
                }
                *(float2*)&C[(size_t)r0 * N + c] = v0;
                *(float2*)&C[(size_t)r1 * N + c] = v1;
            }
        }
    }
}

// ---------------------------------------------------------------------------
// Weight packing: fp32 [K][N] -> bf16x2 [K/2][N]
// ---------------------------------------------------------------------------
__global__ void pack_wbf16(const float* __restrict__ W, uint32_t* __restrict__ Bp,
                           int K, int N)
{
    int i = blockIdx.x * blockDim.x + threadIdx.x;
    if (i >= (K / 2) * N) return;
    int kp = i / N, n = i - kp * N;
    Bp[i] = pack2(W[(2 * kp) * N + n], W[(2 * kp + 1) * N + n]);
}

__global__ void pack_small(const float* __restrict__ W_off, const float* __restrict__ b_off,
                           const float* __restrict__ W_attn, const float* __restrict__ b_attn,
                           float* __restrict__ Wp, float* __restrict__ bp)
{
    int i = blockIdx.x * blockDim.x + threadIdx.x;
    int k = i / 96, n = i - k * 96;
    Wp[i] = (n < 64) ? W_off[k * 64 + n] : W_attn[k * 32 + (n - 64)];
    if (i < 96) bp[i] = (i < 64) ? b_off[i] : b_attn[i - 64];
}

// ---------------------------------------------------------------------------
// Deformable bilinear sampling + per-head softmax. Branch-free clamped
// gathers (full MLP). Output written as packed bf16x2 for GEMM3.
// ---------------------------------------------------------------------------
__global__ __launch_bounds__(256, 5) void sample_kernel(
    const float* __restrict__ v, const float* __restrict__ offlg,
    uint32_t* __restrict__ outb,
    const int* __restrict__ hptr, const int* __restrict__ wptr)
{
    const int h = *hptr, w = *wptr;
    const int HW = h * w;
    const int tid  = threadIdx.x;
    const int row  = blockIdx.x * 4 + (tid >> 6);
    const int t    = tid & 63;
    const int head = t >> 3;
    const int l8   = t & 7;

    const int b  = row / HW;
    const int q  = row - b * HW;
    const int qy = q / w;
    const int qx = q - qy * w;

    const float* base = offlg + row * 96;
    float4 lgv = *(const float4*)(base + 64 + head * 4);
    float4 o01 = *(const float4*)(base + head * 8);
    float4 o23 = *(const float4*)(base + head * 8 + 4);

    float mx = fmaxf(fmaxf(lgv.x, lgv.y), fmaxf(lgv.z, lgv.w));
    float e0 = __expf(lgv.x - mx), e1 = __expf(lgv.y - mx);
    float e2 = __expf(lgv.z - mx), e3 = __expf(lgv.w - mx);
    float inv = 1.f / (e0 + e1 + e2 + e3);
    float aw[PTS] = {e0 * inv, e1 * inv, e2 * inv, e3 * inv};
    float ofx[PTS] = {o01.x, o01.z, o23.x, o23.z};
    float ofy[PTS] = {o01.y, o01.w, o23.y, o23.w};

    const float* vb = v + ((b * HW) << 8) + head * 32 + l8 * 4;

    float4 acc = make_float4(0.f, 0.f, 0.f, 0.f);
#pragma unroll
    for (int p = 0; p < PTS; p++) {
        float ix = (float)qx + ofx[p];
        float iy = (float)qy + ofy[p];
        float xf = floorf(ix), yf = floorf(iy);
        int x0 = (int)xf, y0 = (int)yf;
        float wx1 = ix - xf, wy1 = iy - yf;
        float wx0 = 1.f - wx1, wy0 = 1.f - wy1;

        bool vx0 = (unsigned)x0 < (unsigned)w;
        bool vx1 = (unsigned)(x0 + 1) < (unsigned)w;
        bool vy0 = (unsigned)y0 < (unsigned)h;
        bool vy1 = (unsigned)(y0 + 1) < (unsigned)h;

        // clamp indices; zero weights outside — loads become branch-free
        int x0c = min(max(x0, 0), w - 1);
        int x1c = min(max(x0 + 1, 0), w - 1);
        int y0c = min(max(y0, 0), h - 1);
        int y1c = min(max(y0 + 1, 0), h - 1);

        float w00 = (vy0 && vx0) ? wx0 * wy0 * aw[p] : 0.f;
        float w01 = (vy0 && vx1) ? wx1 * wy0 * aw[p] : 0.f;
        float w10 = (vy1 && vx0) ? wx0 * wy1 * aw[p] : 0.f;
        float w11 = (vy1 && vx1) ? wx1 * wy1 * aw[p] : 0.f;

        int r0 = (y0c * w) << 8, r1 = (y1c * w) << 8;
        float4 c00 = *(const float4*)(vb + r0 + (x0c << 8));
        float4 c01 = *(const float4*)(vb + r0 + (x1c << 8));
        float4 c10 = *(const float4*)(vb + r1 + (x0c << 8));
        float4 c11 = *(const float4*)(vb + r1 + (x1c << 8));

        acc.x = fmaf(w00, c00.x, acc.x); acc.y = fmaf(w00, c00.y, acc.y);
        acc.z = fmaf(w00, c00.z, acc.z); acc.w = fmaf(w00, c00.w, acc.w);
        acc.x = fmaf(w01, c01.x, acc.x); acc.y = fmaf(w01, c01.y, acc.y);
        acc.z = fmaf(w01, c01.z, acc.z); acc.w = fmaf(w01, c01.w, acc.w);
        acc.x = fmaf(w10, c10.x, acc.x); acc.y = fmaf(w10, c10.y, acc.y);
        acc.z = fmaf(w10, c10.z, acc.z); acc.w = fmaf(w10, c10.w, acc.w);
        acc.x = fmaf(w11, c11.x, acc.x); acc.y = fmaf(w11, c11.y, acc.y);
        acc.z = fmaf(w11, c11.z, acc.z); acc.w = fmaf(w11, c11.w, acc.w);
    }
    uint2 pk;
    pk.x = pack2(acc.x, acc.y);
    pk.y = pack2(acc.z, acc.w);
    *(uint2*)(outb + (row << 7) + head * 16 + l8 * 2) = pk;
}

// ---------------------------------------------------------------------------

extern "C" void kernel_launch(void* const* d_in, const int* in_sizes, int n_in,
                              void* d_out, int out_size)
{
    const float* query  = (const float*)d_in[0];
    const float* value  = (const float*)d_in[1];
    const float* W_off  = (const float*)d_in[2];
    const float* b_off  = (const float*)d_in[3];
    const float* W_attn = (const float*)d_in[4];
    const float* b_attn = (const float*)d_in[5];
    const float* W_val  = (const float*)d_in[6];
    const float* b_val  = (const float*)d_in[7];
    const float* W_out  = (const float*)d_in[8];
    const float* b_out  = (const float*)d_in[9];
    const int*   hp     = (const int*)d_in[10];
    const int*   wp     = (const int*)d_in[11];
    float* out = (float*)d_out;

    const int K = in_sizes[2] / (HEADS * PTS * 2);   // 256
    const int M = in_sizes[0] / K;                   // 32768
    const int N = in_sizes[6] / K;                   // 256

    float *gv, *gofflg, *gWp, *gbp;
    uint32_t *gattnb, *gWvalp, *gWoutp;
    cudaGetSymbolAddress((void**)&gv,     g_v);
    cudaGetSymbolAddress((void**)&gofflg, g_offlg);
    cudaGetSymbolAddress((void**)&gattnb, g_attnb);
    cudaGetSymbolAddress((void**)&gWp,    g_Wp);
    cudaGetSymbolAddress((void**)&gbp,    g_bp);
    cudaGetSymbolAddress((void**)&gWvalp, g_Wvalp);
    cudaGetSymbolAddress((void**)&gWoutp, g_Woutp);

    cudaFuncSetAttribute(gemm_tf32, cudaFuncAttributeMaxDynamicSharedMemorySize, GEMM_SMEM);
    cudaFuncSetAttribute(gemm_bf16<false>, cudaFuncAttributeMaxDynamicSharedMemorySize, SMEM_GF);
    cudaFuncSetAttribute(gemm_bf16<true>,  cudaFuncAttributeMaxDynamicSharedMemorySize, SMEM_GH);

    const int nw = (K / 2) * N;  // packed words per 256x256 weight

    // Fork: value path on side stream, query path on main stream.
    cudaEventRecord(e_fork, 0);
    cudaStreamWaitEvent(s_side, e_fork, 0);

    // side: pack W_val, then v = value @ W_val + b_val (bf16 MMA, fp32 A)
    pack_wbf16<<<(nw + 255) / 256, 256, 0, s_side>>>(W_val, gWvalp, K, N);
    gemm_bf16<false><<<dim3(N / 128, M / 128), 256, SMEM_GF, s_side>>>(
        value, gWvalp, b_val, nullptr, gv, M, N, K);
    cudaEventRecord(e_join, s_side);

    // main: [off|logits] = query @ [W_off|W_attn] (tf32 — error-sensitive),
    //       and pack W_out for later.
    pack_small<<<(K * 96) / 256, 256>>>(W_off, b_off, W_attn, b_attn, gWp, gbp);
    pack_wbf16<<<(nw + 255) / 256, 256>>>(W_out, gWoutp, K, N);
    gemm_tf32<<<dim3(1, M / 128), 256, GEMM_SMEM>>>(query, gWp, gbp, nullptr, gofflg, M, 96, K);

    // join, then sampling (bf16 out) + output GEMM (bf16 A)
    cudaStreamWaitEvent(0, e_join, 0);
    sample_kernel<<<M / 4, 256>>>(gv, gofflg, gattnb, hp, wp);
    gemm_bf16<true><<<dim3(N / 128, M / 128), 256, SMEM_GH>>>(
        gattnb, gWoutp, b_out, query, out, M, N, K);
}

// round 6
// speedup vs baseline: 3.2605x; 1.0026x over previous
#include <cuda_runtime.h>
#include <cuda_bf16.h>
#include <math.h>
#include <stdint.h>

#define HEADS   8
#define PTS     4
#define CH      256
#define MAXROWS 32768

// Scratch (__device__ globals per allocation-free rule)
__device__ float    g_v[MAXROWS * CH];          // value @ W_val (fp32)
__device__ float    g_offlg[MAXROWS * 96];      // [off(64) | logits(32)] per row
__device__ uint32_t g_attnb[MAXROWS * CH / 2];  // sampled output, packed bf16x2
__device__ float    g_Wp[CH * 96];              // packed fp32 [W_off | W_attn]
__device__ float    g_bp[96];
__device__ uint32_t g_Wvalp[CH * CH / 2];       // bf16x2-packed weights
__device__ uint32_t g_Woutp[CH * CH / 2];

// Streams/events for fork-join inside graph capture (created before capture).
static cudaStream_t s_side = nullptr;
static cudaEvent_t  e_fork = nullptr, e_join = nullptr;
namespace {
struct StreamInit {
    StreamInit() {
        cudaStreamCreateWithFlags(&s_side, cudaStreamNonBlocking);
        cudaEventCreateWithFlags(&e_fork, cudaEventDisableTiming);
        cudaEventCreateWithFlags(&e_join, cudaEventDisableTiming);
    }
} s_init;
}

__device__ __forceinline__ uint32_t f2tf32(float x) {
    uint32_t r;
    asm("cvt.rna.tf32.f32 %0, %1;" : "=r"(r) : "f"(x));
    return r;
}
// pack2(lo, hi): lo -> bits[0:16), hi -> bits[16:32)
__device__ __forceinline__ uint32_t pack2(float lo, float hi) {
    uint32_t r;
    asm("cvt.rn.bf16x2.f32 %0, %1, %2;" : "=r"(r) : "f"(hi), "f"(lo));
    return r;
}
__device__ __forceinline__ void cpasync16(void* dst_smem, const void* src, bool pred) {
    uint32_t d = (uint32_t)__cvta_generic_to_shared(dst_smem);
    int sz = pred ? 16 : 0;
    asm volatile("cp.async.cg.shared.global [%0], [%1], 16, %2;\n"
                 :: "r"(d), "l"(src), "r"(sz));
}

// ===========================================================================
// bf16 tensor-core GEMM (m16n8k16), cp.async 3-stage pipelined.
// C[M,N](fp32) = A[M,K] @ B[K,N] + bias (+ resid). B pre-packed bf16x2 [K/2][N].
// A: fp32 (convert at frag read) if !ABF16, else bf16 row-major.
// Block 128x128x32, 8 warps (2m x 4n), warp tile 64x32.
// ===========================================================================
#define ALD_F 40            // fp32 A row pad (words)
#define ALD_H 20            // bf16 A row pad (words)
#define BLD   136           // B row pad (words)
#define ASZ_F (128 * ALD_F)
#define ASZ_H (128 * ALD_H)
#define BSZP  (16 * BLD)
#define NSTG  3
#define SMEM_GF ((NSTG * ASZ_F + NSTG * BSZP) * 4)
#define SMEM_GH ((NSTG * ASZ_H + NSTG * BSZP) * 4)

template<bool ABF16>
__global__ __launch_bounds__(256) void gemm_bf16(
    const void* __restrict__ Av, const uint32_t* __restrict__ Bp,
    const float* __restrict__ bias, const float* __restrict__ resid,
    float* __restrict__ C, int M, int N, int K)
{
    extern __shared__ __align__(16) uint32_t smemw[];
    const int ASZ = ABF16 ? ASZ_H : ASZ_F;
    uint32_t* Asm = smemw;
    uint32_t* Bsm = smemw + NSTG * ASZ;

    const int tid  = threadIdx.x;
    const int lane = tid & 31;
    const int warp = tid >> 5;
    const int wm   = warp & 1;
    const int wn   = warp >> 1;
    const int m0   = blockIdx.y * 128;
    const int n0   = blockIdx.x * 128;
    const int lr   = lane >> 2;
    const int lc   = lane & 3;

    float acc[4][4][4];
#pragma unroll
    for (int i = 0; i < 4; i++)
#pragma unroll
        for (int j = 0; j < 4; j++)
#pragma unroll
            for (int v = 0; v < 4; v++) acc[i][j][v] = 0.f;

    const int nk = K >> 5;

    auto stage_load = [&](int s, int k0) {
        uint32_t* As = Asm + s * ASZ;
        uint32_t* Bs = Bsm + s * BSZP;
        if (ABF16) {
            const __nv_bfloat16* A = (const __nv_bfloat16*)Av;
#pragma unroll
            for (int i = 0; i < 2; i++) {
                int f = tid + i * 256;
                int r = f >> 2, c = f & 3;
                cpasync16(&As[r * ALD_H + c * 4],
                          &A[(size_t)(m0 + r) * K + k0 + c * 8], true);
            }
        } else {
            const float* A = (const float*)Av;
#pragma unroll
            for (int i = 0; i < 4; i++) {
                int f = tid + i * 256;
                int r = f >> 3, c4 = f & 7;
                cpasync16(&As[r * ALD_F + c4 * 4],
                          &A[(size_t)(m0 + r) * K + k0 + c4 * 4], true);
            }
        }
#pragma unroll
        for (int i = 0; i < 2; i++) {
            int f  = tid + i * 256;
            int kp = f >> 5;
            int c4 = f & 31;
            int n  = n0 + c4 * 4;
            cpasync16(&Bs[kp * BLD + c4 * 4],
                      &Bp[(size_t)((k0 >> 1) + kp) * N + n], n < N);
        }
        asm volatile("cp.async.commit_group;\n");
    };

    stage_load(0, 0);
    if (nk > 1) stage_load(1, 32);

    uint32_t af[2][4][4];
    uint32_t bf[2][4][2];

    auto frag_load = [&](const uint32_t* As, const uint32_t* Bs, int buf, int ks) {
#pragma unroll
        for (int ma = 0; ma < 4; ma++) {
            int r = wm * 64 + ma * 16 + lr;
            if (ABF16) {
                af[buf][ma][0] = As[r * ALD_H + (ks >> 1) + lc];
                af[buf][ma][1] = As[(r + 8) * ALD_H + (ks >> 1) + lc];
                af[buf][ma][2] = As[r * ALD_H + (ks >> 1) + 4 + lc];
                af[buf][ma][3] = As[(r + 8) * ALD_H + (ks >> 1) + 4 + lc];
            } else {
                const float* Af = (const float*)As;
                float2 a0 = *(const float2*)&Af[r * ALD_F + ks + 2 * lc];
                float2 a1 = *(const float2*)&Af[(r + 8) * ALD_F + ks + 2 * lc];
                float2 a2 = *(const float2*)&Af[r * ALD_F + ks + 8 + 2 * lc];
                float2 a3 = *(const float2*)&Af[(r + 8) * ALD_F + ks + 8 + 2 * lc];
                af[buf][ma][0] = pack2(a0.x, a0.y);
                af[buf][ma][1] = pack2(a1.x, a1.y);
                af[buf][ma][2] = pack2(a2.x, a2.y);
                af[buf][ma][3] = pack2(a3.x, a3.y);
            }
        }
#pragma unroll
        for (int na = 0; na < 4; na++) {
            int n = wn * 32 + na * 8 + lr;
            bf[buf][na][0] = Bs[((ks >> 1) + lc) * BLD + n];
            bf[buf][na][1] = Bs[((ks >> 1) + 4 + lc) * BLD + n];
        }
    };

    for (int kt = 0; kt < nk; kt++) {
        if (kt + 1 < nk) asm volatile("cp.async.wait_group 1;\n");
        else             asm volatile("cp.async.wait_group 0;\n");
        __syncthreads();
        if (kt + 2 < nk) stage_load((kt + 2) % NSTG, (kt + 2) * 32);

        const uint32_t* As = Asm + (kt % NSTG) * ASZ;
        const uint32_t* Bs = Bsm + (kt % NSTG) * BSZP;

        frag_load(As, Bs, 0, 0);
#pragma unroll
        for (int s = 0; s < 2; s++) {
            int cur = s & 1, nxt = cur ^ 1;
            if (s == 0) frag_load(As, Bs, nxt, 16);
#pragma unroll
            for (int ma = 0; ma < 4; ma++)
#pragma unroll
                for (int na = 0; na < 4; na++) {
                    asm volatile(
                        "mma.sync.aligned.m16n8k16.row.col.f32.bf16.bf16.f32 "
                        "{%0,%1,%2,%3}, {%4,%5,%6,%7}, {%8,%9}, {%0,%1,%2,%3};\n"
                        : "+f"(acc[ma][na][0]), "+f"(acc[ma][na][1]),
                          "+f"(acc[ma][na][2]), "+f"(acc[ma][na][3])
                        : "r"(af[cur][ma][0]), "r"(af[cur][ma][1]),
                          "r"(af[cur][ma][2]), "r"(af[cur][ma][3]),
                          "r"(bf[cur][na][0]), "r"(bf[cur][na][1]));
                }
        }
        __syncthreads();
    }

#pragma unroll
    for (int ma = 0; ma < 4; ma++) {
        int r0 = m0 + wm * 64 + ma * 16 + lr;
        int r1 = r0 + 8;
#pragma unroll
        for (int na = 0; na < 4; na++) {
            int c = n0 + wn * 32 + na * 8 + lc * 2;
            if (c < N) {
                float2 bv = *(const float2*)&bias[c];
                float2 v0 = make_float2(acc[ma][na][0] + bv.x, acc[ma][na][1] + bv.y);
                float2 v1 = make_float2(acc[ma][na][2] + bv.x, acc[ma][na][3] + bv.y);
                if (resid) {
                    float2 r0v = *(const float2*)&resid[(size_t)r0 * N + c];
                    float2 r1v = *(const float2*)&resid[(size_t)r1 * N + c];
                    v0.x += r0v.x; v0.y += r0v.y;
                    v1.x += r1v.x; v1.y += r1v.y;
                }
                *(float2*)&C[(size_t)r0 * N + c] = v0;
                *(float2*)&C[(size_t)r1 * N + c] = v1;
            }
        }
    }
}

// ===========================================================================
// tf32 GEMM (small offsets/logits GEMM — error-sensitive path; hidden by fork)
// ===========================================================================
#define AS_LD 36
#define BS_LD 136
#define ASZ32 (128 * AS_LD)
#define BSZ32 (32 * BS_LD)
#define GEMM_SMEM ((2 * ASZ32 + 2 * BSZ32) * 4)

__global__ __launch_bounds__(256) void gemm_tf32(
    const float* __restrict__ A, const float* __restrict__ B,
    const float* __restrict__ bias, const float* __restrict__ resid,
    float* __restrict__ C, int M, int N, int K)
{
    extern __shared__ __align__(16) float smem[];
    float* Asm = smem;
    float* Bsm = smem + 2 * ASZ32;

    const int tid  = threadIdx.x;
    const int lane = tid & 31;
    const int warp = tid >> 5;
    const int wm   = warp & 1;
    const int wn   = warp >> 1;
    const int m0   = blockIdx.y * 128;
    const int n0   = blockIdx.x * 128;
    const int lr   = lane >> 2;
    const int lc   = lane & 3;

    float acc[4][4][4];
#pragma unroll
    for (int i = 0; i < 4; i++)
#pragma unroll
        for (int j = 0; j < 4; j++)
#pragma unroll
            for (int v = 0; v < 4; v++) acc[i][j][v] = 0.f;

    const int nk = K >> 5;

    auto stage_load = [&](int s, int k0) {
        float* As = Asm + s * ASZ32;
        float* Bs = Bsm + s * BSZ32;
#pragma unroll
        for (int i = 0; i < 4; i++) {
            int f  = tid + i * 256;
            int r  = f >> 3;
            int c4 = f & 7;
            cpasync16(&As[r * AS_LD + c4 * 4],
                      &A[(size_t)(m0 + r) * K + k0 + c4 * 4], true);
        }
#pragma unroll
        for (int i = 0; i < 4; i++) {
            int f  = tid + i * 256;
            int kk = f >> 5;
            int c4 = f & 31;
            cpasync16(&Bs[kk * BS_LD + c4 * 4],
                      &B[(size_t)(k0 + kk) * N + n0 + c4 * 4],
                      (n0 + c4 * 4) < N);
        }
        asm volatile("cp.async.commit_group;\n");
    };

    stage_load(0, 0);

    uint32_t af[2][4][4];
    uint32_t bf[2][4][2];

    for (int kt = 0; kt < nk; kt++) {
        asm volatile("cp.async.wait_group 0;\n");
        __syncthreads();
        if (kt + 1 < nk) stage_load((kt + 1) & 1, (kt + 1) * 32);

        const float* As = Asm + (kt & 1) * ASZ32;
        const float* Bs = Bsm + (kt & 1) * BSZ32;

#pragma unroll
        for (int ma = 0; ma < 4; ma++) {
            int r = wm * 64 + ma * 16 + lr;
            af[0][ma][0] = f2tf32(As[r * AS_LD + lc]);
            af[0][ma][1] = f2tf32(As[(r + 8) * AS_LD + lc]);
            af[0][ma][2] = f2tf32(As[r * AS_LD + 4 + lc]);
            af[0][ma][3] = f2tf32(As[(r + 8) * AS_LD + 4 + lc]);
        }
#pragma unroll
        for (int na = 0; na < 4; na++) {
            int n = wn * 32 + na * 8 + lr;
            bf[0][na][0] = f2tf32(Bs[lc * BS_LD + n]);
            bf[0][na][1] = f2tf32(Bs[(4 + lc) * BS_LD + n]);
        }

#pragma unroll
        for (int s = 0; s < 4; s++) {
            int cur = s & 1, nxt = cur ^ 1;
            if (s < 3) {
                int ks = (s + 1) * 8;
#pragma unroll
                for (int ma = 0; ma < 4; ma++) {
                    int r = wm * 64 + ma * 16 + lr;
                    af[nxt][ma][0] = f2tf32(As[r * AS_LD + ks + lc]);
                    af[nxt][ma][1] = f2tf32(As[(r + 8) * AS_LD + ks + lc]);
                    af[nxt][ma][2] = f2tf32(As[r * AS_LD + ks + 4 + lc]);
                    af[nxt][ma][3] = f2tf32(As[(r + 8) * AS_LD + ks + 4 + lc]);
                }
#pragma unroll
                for (int na = 0; na < 4; na++) {
                    int n = wn * 32 + na * 8 + lr;
                    bf[nxt][na][0] = f2tf32(Bs[(ks + lc) * BS_LD + n]);
                    bf[nxt][na][1] = f2tf32(Bs[(ks + 4 + lc) * BS_LD + n]);
                }
            }
#pragma unroll
            for (int ma = 0; ma < 4; ma++)
#pragma unroll
                for (int na = 0; na < 4; na++) {
                    asm volatile(
                        "mma.sync.aligned.m16n8k8.row.col.f32.tf32.tf32.f32 "
                        "{%0,%1,%2,%3}, {%4,%5,%6,%7}, {%8,%9}, {%0,%1,%2,%3};\n"
                        : "+f"(acc[ma][na][0]), "+f"(acc[ma][na][1]),
                          "+f"(acc[ma][na][2]), "+f"(acc[ma][na][3])
                        : "r"(af[cur][ma][0]), "r"(af[cur][ma][1]),
                          "r"(af[cur][ma][2]), "r"(af[cur][ma][3]),
                          "r"(bf[cur][na][0]), "r"(bf[cur][na][1]));
                }
        }
        __syncthreads();
    }

#pragma unroll
    for (int ma = 0; ma < 4; ma++) {
        int r0 = m0 + wm * 64 + ma * 16 + lr;
        int r1 = r0 + 8;
#pragma unroll
        for (int na = 0; na < 4; na++) {
            int c = n0 + wn * 32 + na * 8 + lc * 2;
            if (c < N) {
                float2 bv = *(const float2*)&bias[c];
                float2 v0 = make_float2(acc[ma][na][0] + bv.x, acc[ma][na][1] + bv.y);
                float2 v1 = make_float2(acc[ma][na][2] + bv.x, acc[ma][na][3] + bv.y);
                if (resid) {
                    float2 r0v = *(const float2*)&resid[(size_t)r0 * N + c];
                    float2 r1v = *(const float2*)&resid[(size_t)r1 * N + c];
                    v0.x += r0v.x; v0.y += r0v.y;
                    v1.x += r1v.x; v1.y += r1v.y;
                }
                *(float2*)&C[(size_t)r0 * N + c] = v0;
                *(float2*)&C[(size_t)r1 * N + c] = v1;
            }
        }
    }
}

// ---------------------------------------------------------------------------
// Weight packing: fp32 [K][N] -> bf16x2 [K/2][N], vectorized float4/uint4.
// One thread handles 4 consecutive n at one k-pair. Threads = (K/2)*(N/4).
// ---------------------------------------------------------------------------
__global__ void pack_wbf16(const float* __restrict__ W, uint32_t* __restrict__ Bp,
                           int K, int N)
{
    int i = blockIdx.x * blockDim.x + threadIdx.x;
    if (i >= (K / 2) * (N / 4)) return;
    int kp = i / (N / 4);
    int c  = (i - kp * (N / 4)) * 4;
    float4 a = *(const float4*)&W[(size_t)(2 * kp) * N + c];
    float4 b = *(const float4*)&W[(size_t)(2 * kp + 1) * N + c];
    uint4 o;
    o.x = pack2(a.x, b.x);
    o.y = pack2(a.y, b.y);
    o.z = pack2(a.z, b.z);
    o.w = pack2(a.w, b.w);
    *(uint4*)&Bp[(size_t)kp * N + c] = o;
}

__global__ void pack_small(const float* __restrict__ W_off, const float* __restrict__ b_off,
                           const float* __restrict__ W_attn, const float* __restrict__ b_attn,
                           float* __restrict__ Wp, float* __restrict__ bp)
{
    int i = blockIdx.x * blockDim.x + threadIdx.x;
    int k = i / 96, n = i - k * 96;
    Wp[i] = (n < 64) ? W_off[k * 64 + n] : W_attn[k * 32 + (n - 64)];
    if (i < 96) bp[i] = (i < 64) ? b_off[i] : b_attn[i - 64];
}

// ---------------------------------------------------------------------------
// Deformable bilinear sampling + per-head softmax. Branch-free clamped
// gathers, batched two points at a time (8 loads in flight) for MLP.
// Output written as packed bf16x2 for GEMM3.
// ---------------------------------------------------------------------------
__global__ __launch_bounds__(256, 5) void sample_kernel(
    const float* __restrict__ v, const float* __restrict__ offlg,
    uint32_t* __restrict__ outb,
    const int* __restrict__ hptr, const int* __restrict__ wptr)
{
    const int h = *hptr, w = *wptr;
    const int HW = h * w;
    const int tid  = threadIdx.x;
    const int row  = blockIdx.x * 4 + (tid >> 6);
    const int t    = tid & 63;
    const int head = t >> 3;
    const int l8   = t & 7;

    const int b  = row / HW;
    const int q  = row - b * HW;
    const int qy = q / w;
    const int qx = q - qy * w;

    const float* base = offlg + row * 96;
    float4 lgv = *(const float4*)(base + 64 + head * 4);
    float4 o01 = *(const float4*)(base + head * 8);
    float4 o23 = *(const float4*)(base + head * 8 + 4);

    float mx = fmaxf(fmaxf(lgv.x, lgv.y), fmaxf(lgv.z, lgv.w));
    float e0 = __expf(lgv.x - mx), e1 = __expf(lgv.y - mx);
    float e2 = __expf(lgv.z - mx), e3 = __expf(lgv.w - mx);
    float inv = 1.f / (e0 + e1 + e2 + e3);
    float aw[PTS] = {e0 * inv, e1 * inv, e2 * inv, e3 * inv};
    float ofx[PTS] = {o01.x, o01.z, o23.x, o23.z};
    float ofy[PTS] = {o01.y, o01.w, o23.y, o23.w};

    const float* vb = v + ((b * HW) << 8) + head * 32 + l8 * 4;

    float4 acc = make_float4(0.f, 0.f, 0.f, 0.f);

#pragma unroll
    for (int pb = 0; pb < PTS; pb += 2) {
        int   offs[8];
        float wgt[8];
#pragma unroll
        for (int pi = 0; pi < 2; pi++) {
            int p = pb + pi;
            float ix = (float)qx + ofx[p];
            float iy = (float)qy + ofy[p];
            float xf = floorf(ix), yf = floorf(iy);
            int x0 = (int)xf, y0 = (int)yf;
            float wx1 = ix - xf, wy1 = iy - yf;
            float wx0 = 1.f - wx1, wy0 = 1.f - wy1;

            bool vx0 = (unsigned)x0 < (unsigned)w;
            bool vx1 = (unsigned)(x0 + 1) < (unsigned)w;
            bool vy0 = (unsigned)y0 < (unsigned)h;
            bool vy1 = (unsigned)(y0 + 1) < (unsigned)h;

            int x0c = min(max(x0, 0), w - 1);
            int x1c = min(max(x0 + 1, 0), w - 1);
            int y0c = min(max(y0, 0), h - 1);
            int y1c = min(max(y0 + 1, 0), h - 1);

            wgt[pi * 4 + 0] = (vy0 && vx0) ? wx0 * wy0 * aw[p] : 0.f;
            wgt[pi * 4 + 1] = (vy0 && vx1) ? wx1 * wy0 * aw[p] : 0.f;
            wgt[pi * 4 + 2] = (vy1 && vx0) ? wx0 * wy1 * aw[p] : 0.f;
            wgt[pi * 4 + 3] = (vy1 && vx1) ? wx1 * wy1 * aw[p] : 0.f;

            int r0 = (y0c * w) << 8, r1 = (y1c * w) << 8;
            offs[pi * 4 + 0] = r0 + (x0c << 8);
            offs[pi * 4 + 1] = r0 + (x1c << 8);
            offs[pi * 4 + 2] = r1 + (x0c << 8);
            offs[pi * 4 + 3] = r1 + (x1c << 8);
        }

        float4 c[8];
#pragma unroll
        for (int i = 0; i < 8; i++) c[i] = *(const float4*)(vb + offs[i]);
#pragma unroll
        for (int i = 0; i < 8; i++) {
            acc.x = fmaf(wgt[i], c[i].x, acc.x);
            acc.y = fmaf(wgt[i], c[i].y, acc.y);
            acc.z = fmaf(wgt[i], c[i].z, acc.z);
            acc.w = fmaf(wgt[i], c[i].w, acc.w);
        }
    }
    uint2 pk;
    pk.x = pack2(acc.x, acc.y);
    pk.y = pack2(acc.z, acc.w);
    *(uint2*)(outb + (row << 7) + head * 16 + l8 * 2) = pk;
}

// ---------------------------------------------------------------------------

extern "C" void kernel_launch(void* const* d_in, const int* in_sizes, int n_in,
                              void* d_out, int out_size)
{
    const float* query  = (const float*)d_in[0];
    const float* value  = (const float*)d_in[1];
    const float* W_off  = (const float*)d_in[2];
    const float* b_off  = (const float*)d_in[3];
    const float* W_attn = (const float*)d_in[4];
    const float* b_attn = (const float*)d_in[5];
    const float* W_val  = (const float*)d_in[6];
    const float* b_val  = (const float*)d_in[7];
    const float* W_out  = (const float*)d_in[8];
    const float* b_out  = (const float*)d_in[9];
    const int*   hp     = (const int*)d_in[10];
    const int*   wp     = (const int*)d_in[11];
    float* out = (float*)d_out;

    const int K = in_sizes[2] / (HEADS * PTS * 2);   // 256
    const int M = in_sizes[0] / K;                   // 32768
    const int N = in_sizes[6] / K;                   // 256

    float *gv, *gofflg, *gWp, *gbp;
    uint32_t *gattnb, *gWvalp, *gWoutp;
    cudaGetSymbolAddress((void**)&gv,     g_v);
    cudaGetSymbolAddress((void**)&gofflg, g_offlg);
    cudaGetSymbolAddress((void**)&gattnb, g_attnb);
    cudaGetSymbolAddress((void**)&gWp,    g_Wp);
    cudaGetSymbolAddress((void**)&gbp,    g_bp);
    cudaGetSymbolAddress((void**)&gWvalp, g_Wvalp);
    cudaGetSymbolAddress((void**)&gWoutp, g_Woutp);

    cudaFuncSetAttribute(gemm_tf32, cudaFuncAttributeMaxDynamicSharedMemorySize, GEMM_SMEM);
    cudaFuncSetAttribute(gemm_bf16<false>, cudaFuncAttributeMaxDynamicSharedMemorySize, SMEM_GF);
    cudaFuncSetAttribute(gemm_bf16<true>,  cudaFuncAttributeMaxDynamicSharedMemorySize, SMEM_GH);

    const int npk = (K / 2) * (N / 4);  // pack threads per 256x256 weight

    // Fork: value path on side stream, query path on main stream.
    cudaEventRecord(e_fork, 0);
    cudaStreamWaitEvent(s_side, e_fork, 0);

    // side: pack W_val, then v = value @ W_val + b_val (bf16 MMA, fp32 A)
    pack_wbf16<<<(npk + 255) / 256, 256, 0, s_side>>>(W_val, gWvalp, K, N);
    gemm_bf16<false><<<dim3(N / 128, M / 128), 256, SMEM_GF, s_side>>>(
        value, gWvalp, b_val, nullptr, gv, M, N, K);
    cudaEventRecord(e_join, s_side);

    // main: [off|logits] = query @ [W_off|W_attn] (tf32 — error-sensitive),
    //       and pack W_out for later.
    pack_small<<<(K * 96) / 256, 256>>>(W_off, b_off, W_attn, b_attn, gWp, gbp);
    pack_wbf16<<<(npk + 255) / 256, 256>>>(W_out, gWoutp, K, N);
    gemm_tf32<<<dim3(1, M / 128), 256, GEMM_SMEM>>>(query, gWp, gbp, nullptr, gofflg, M, 96, K);

    // join, then sampling (bf16 out) + output GEMM (bf16 A)
    cudaStreamWaitEvent(0, e_join, 0);
    sample_kernel<<<M / 4, 256>>>(gv, gofflg, gattnb, hp, wp);
    gemm_bf16<true><<<dim3(N / 128, M / 128), 256, SMEM_GH>>>(
        gattnb, gWoutp, b_out, query, out, M, N, K);
}